// round 4
// baseline (speedup 1.0000x reference)
#include <cuda_runtime.h>

#define NN 100000
#define EE 1600000
#define ET (EE + NN)        // 1,700,000 edges incl self loops
#define HIDD 128
#define NHEAD 4
#define HDIM 32
#define NG 128
#define NEG 0.2f
#define BNEPS 1e-5f

// ---------------- scratch (device globals; no dynamic allocation) ----------
__device__ float g_h[(size_t)NN * HIDD];     // per-layer transformed features
__device__ float g_bufA[(size_t)NN * HIDD];  // ping
__device__ float g_bufB[(size_t)NN * HIDD];  // pong
__device__ float g_as[NN * NHEAD];
__device__ float g_ad[NN * NHEAD];
__device__ float g_e[(size_t)ET * NHEAD];    // per-edge logits -> probs
__device__ float g_emax[NN * NHEAD];
__device__ float g_den[NN * NHEAD];
__device__ int   g_src[ET];
__device__ int   g_dst[ET];
__device__ int   g_batch[NN];
__device__ float g_sums[NG * HIDD];
__device__ float g_cnts[NG];
__device__ int   g_i64;

// ---------------- helpers ---------------------------------------------------
__device__ __forceinline__ float lrelu(float v) { return v > 0.f ? v : NEG * v; }

__device__ __forceinline__ void atomicMaxF(float* a, float v) {
    if (v >= 0.f) atomicMax((int*)a, __float_as_int(v));
    else          atomicMin((unsigned int*)a, __float_as_uint(v));
}

__device__ __forceinline__ float* accbuf(int sel) { return sel == 0 ? g_bufA : g_bufB; }

// ---------------- dtype detection + index conversion ------------------------
__global__ void k_detect(const int* ei) {
    // int64 little-endian: high words (odd int32 slots) of small positive values are 0
    g_i64 = (ei[1] == 0) & (ei[3] == 0) & (ei[5] == 0) & (ei[7] == 0);
}

__global__ void k_convert(const void* ei, const void* bt) {
    long long i = (long long)blockIdx.x * blockDim.x + threadIdx.x;
    int f = g_i64;
    if (i < ET) {
        int s, d;
        if (i < EE) {
            if (f) {
                const long long* p = (const long long*)ei;
                s = (int)p[i]; d = (int)p[EE + i];
            } else {
                const int* p = (const int*)ei;
                s = p[i]; d = p[EE + i];
            }
        } else {
            s = d = (int)(i - EE);   // self loop
        }
        g_src[i] = s; g_dst[i] = d;
    }
    if (i < NN) {
        g_batch[i] = f ? (int)((const long long*)bt)[i] : ((const int*)bt)[i];
    }
}

// ---------------- GEMM: h = X @ W  (128x128 weight) --------------------------
__global__ void k_gemm(const float* __restrict__ Xext, int xsel,
                       const float* __restrict__ W) {
    const float* X = (xsel < 0) ? Xext : (xsel == 0 ? g_bufA : g_bufB);
    __shared__ float Xs[128][17];
    __shared__ float Ws[16][128];
    int t  = threadIdx.x;            // 256 threads
    int tx = t & 15, ty = t >> 4;
    int row0 = blockIdx.x * 128;
    float acc[8][8];
#pragma unroll
    for (int i = 0; i < 8; i++)
#pragma unroll
        for (int j = 0; j < 8; j++) acc[i][j] = 0.f;

    for (int kk = 0; kk < HIDD; kk += 16) {
        // stage X tile [128 x 16]
        int r  = t >> 1;
        int c0 = (t & 1) * 8;
        int gr = row0 + r;
        float v[8];
        if (gr < NN) {
            const float4* p = (const float4*)(X + (size_t)gr * HIDD + kk + c0);
            float4 a = p[0], b = p[1];
            v[0] = a.x; v[1] = a.y; v[2] = a.z; v[3] = a.w;
            v[4] = b.x; v[5] = b.y; v[6] = b.z; v[7] = b.w;
        } else {
#pragma unroll
            for (int i = 0; i < 8; i++) v[i] = 0.f;
        }
#pragma unroll
        for (int i = 0; i < 8; i++) Xs[r][c0 + i] = v[i];
        // stage W tile [16 x 128]
        int wk = t >> 4;
        int wc = (t & 15) * 8;
        const float4* wp = (const float4*)(W + (size_t)(kk + wk) * HIDD + wc);
        *(float4*)&Ws[wk][wc]     = wp[0];
        *(float4*)&Ws[wk][wc + 4] = wp[1];
        __syncthreads();
#pragma unroll
        for (int k = 0; k < 16; k++) {
            float a[8], b[8];
#pragma unroll
            for (int i = 0; i < 8; i++) a[i] = Xs[ty * 8 + i][k];
#pragma unroll
            for (int j = 0; j < 8; j++) b[j] = Ws[k][tx * 8 + j];
#pragma unroll
            for (int i = 0; i < 8; i++)
#pragma unroll
                for (int j = 0; j < 8; j++) acc[i][j] += a[i] * b[j];
        }
        __syncthreads();
    }
#pragma unroll
    for (int i = 0; i < 8; i++) {
        int gr = row0 + ty * 8 + i;
        if (gr < NN) {
            float4* o = (float4*)(g_h + (size_t)gr * HIDD + tx * 8);
            o[0] = make_float4(acc[i][0], acc[i][1], acc[i][2], acc[i][3]);
            o[1] = make_float4(acc[i][4], acc[i][5], acc[i][6], acc[i][7]);
        }
    }
}

// ---------------- attention dot products a_s, a_d ---------------------------
__global__ void k_att(const float* __restrict__ asrc, const float* __restrict__ adst) {
    long long tid = (long long)blockIdx.x * blockDim.x + threadIdx.x;
    int n = (int)(tid >> 5);
    if (n >= NN) return;
    int lane = threadIdx.x & 31;
    int head = lane >> 3;
    int dsub = (lane & 7) * 4;
    float4 hv = *(const float4*)(g_h + (size_t)n * HIDD + head * HDIM + dsub);
    float4 s4 = *(const float4*)(asrc + head * HDIM + dsub);
    float4 d4 = *(const float4*)(adst + head * HDIM + dsub);
    float ps = hv.x * s4.x + hv.y * s4.y + hv.z * s4.z + hv.w * s4.w;
    float pd = hv.x * d4.x + hv.y * d4.y + hv.z * d4.z + hv.w * d4.w;
#pragma unroll
    for (int off = 4; off >= 1; off >>= 1) {
        ps += __shfl_xor_sync(0xffffffffu, ps, off);
        pd += __shfl_xor_sync(0xffffffffu, pd, off);
    }
    if ((lane & 7) == 0) {
        g_as[n * NHEAD + head] = ps;
        g_ad[n * NHEAD + head] = pd;
    }
}

// ---------------- per-layer init: acc=bias, emax=-inf, den=0 ----------------
__global__ void k_init(const float* __restrict__ bias, int sel) {
    int i = blockIdx.x * blockDim.x + threadIdx.x;   // float4 index over NN*32
    if (i >= NN * 32) return;
    float4* acc = (float4*)accbuf(sel);
    acc[i] = ((const float4*)bias)[i & 31];
    if (i < NN) {
        ((float4*)g_emax)[i] = make_float4(-3e38f, -3e38f, -3e38f, -3e38f);
        ((float4*)g_den)[i]  = make_float4(0.f, 0.f, 0.f, 0.f);
    }
}

// ---------------- edge pass 1: logits + segment max -------------------------
__global__ void k_edge1() {
    int e = blockIdx.x * blockDim.x + threadIdx.x;
    if (e >= ET) return;
    int s = g_src[e], d = g_dst[e];
    float4 as4 = *(const float4*)&g_as[s * NHEAD];
    float4 ad4 = *(const float4*)&g_ad[d * NHEAD];
    float4 ev;
    ev.x = lrelu(as4.x + ad4.x);
    ev.y = lrelu(as4.y + ad4.y);
    ev.z = lrelu(as4.z + ad4.z);
    ev.w = lrelu(as4.w + ad4.w);
    *(float4*)&g_e[(size_t)e * NHEAD] = ev;
    float* em = &g_emax[d * NHEAD];
    atomicMaxF(em + 0, ev.x);
    atomicMaxF(em + 1, ev.y);
    atomicMaxF(em + 2, ev.z);
    atomicMaxF(em + 3, ev.w);
}

// ---------------- edge pass 2: exp + segment sum ----------------------------
__global__ void k_edge2() {
    int e = blockIdx.x * blockDim.x + threadIdx.x;
    if (e >= ET) return;
    int d = g_dst[e];
    float4 ev = *(const float4*)&g_e[(size_t)e * NHEAD];
    float4 mx = *(const float4*)&g_emax[d * NHEAD];
    float4 p;
    p.x = __expf(ev.x - mx.x);
    p.y = __expf(ev.y - mx.y);
    p.z = __expf(ev.z - mx.z);
    p.w = __expf(ev.w - mx.w);
    *(float4*)&g_e[(size_t)e * NHEAD] = p;
    float* dn = &g_den[d * NHEAD];
    atomicAdd(dn + 0, p.x);
    atomicAdd(dn + 1, p.y);
    atomicAdd(dn + 2, p.z);
    atomicAdd(dn + 3, p.w);
}

// ---------------- edge pass 3: weighted message aggregation -----------------
// one warp per edge: lane owns 4 contiguous channels (head = lane/8)
__global__ void k_edge3(int sel) {
    long long tid = (long long)blockIdx.x * blockDim.x + threadIdx.x;
    int e = (int)(tid >> 5);
    if (e >= ET) return;
    int lane = threadIdx.x & 31;
    int s = g_src[e], d = g_dst[e];
    int head = lane >> 3;
    float p   = g_e[(size_t)e * NHEAD + head];
    float den = g_den[d * NHEAD + head];
    float alpha = __fdividef(p, den + 1e-16f);
    float4 hv = *(const float4*)(g_h + (size_t)s * HIDD + lane * 4);
    float* dst = accbuf(sel) + (size_t)d * HIDD + lane * 4;
    asm volatile("red.global.add.v4.f32 [%0], {%1,%2,%3,%4};"
                 :: "l"(dst), "f"(hv.x * alpha), "f"(hv.y * alpha),
                    "f"(hv.z * alpha), "f"(hv.w * alpha)
                 : "memory");
}

// ---------------- relu + batchnorm (in-place) -------------------------------
__global__ void k_post(int sel, const float* __restrict__ ga, const float* __restrict__ be,
                       const float* __restrict__ mu, const float* __restrict__ va) {
    int i = blockIdx.x * blockDim.x + threadIdx.x;   // float4 idx over NN*32
    if (i >= NN * 32) return;
    int c4 = i & 31;
    float4* buf = (float4*)accbuf(sel);
    float4 a = buf[i];
    float4 g4 = ((const float4*)ga)[c4];
    float4 b4 = ((const float4*)be)[c4];
    float4 m4 = ((const float4*)mu)[c4];
    float4 v4 = ((const float4*)va)[c4];
    float4 o;
    o.x = (fmaxf(a.x, 0.f) - m4.x) * (g4.x * rsqrtf(v4.x + BNEPS)) + b4.x;
    o.y = (fmaxf(a.y, 0.f) - m4.y) * (g4.y * rsqrtf(v4.y + BNEPS)) + b4.y;
    o.z = (fmaxf(a.z, 0.f) - m4.z) * (g4.z * rsqrtf(v4.z + BNEPS)) + b4.z;
    o.w = (fmaxf(a.w, 0.f) - m4.w) * (g4.w * rsqrtf(v4.w + BNEPS)) + b4.w;
    buf[i] = o;
}

// ---------------- pooling ----------------------------------------------------
__global__ void k_poolinit() {
    int i = blockIdx.x * blockDim.x + threadIdx.x;
    if (i < NG * HIDD) g_sums[i] = 0.f;
    if (i < NG) g_cnts[i] = 0.f;
}

#define POOL_BLOCKS 1024
__global__ void k_pool(int sel) {
    const float* X = (sel == 0) ? g_bufA : g_bufB;
    int c = threadIdx.x;                       // 128 channels
    int chunk = (NN + POOL_BLOCKS - 1) / POOL_BLOCKS;
    int n0 = blockIdx.x * chunk;
    if (n0 >= NN) return;
    int n1 = min(n0 + chunk, NN);
    int g = g_batch[n0];
    float acc = 0.f;
    int cnt = 0;
    for (int n = n0; n < n1; n++) {
        int gn = g_batch[n];
        if (gn != g) {
            atomicAdd(&g_sums[g * HIDD + c], acc);
            if (c == 0) atomicAdd(&g_cnts[g], (float)cnt);
            acc = 0.f; cnt = 0; g = gn;
        }
        acc += X[(size_t)n * HIDD + c];
        cnt++;
    }
    atomicAdd(&g_sums[g * HIDD + c], acc);
    if (c == 0) atomicAdd(&g_cnts[g], (float)cnt);
}

// ---------------- MLP head ---------------------------------------------------
__global__ void k_head(const float* __restrict__ Wh1, const float* __restrict__ bh1,
                       const float* __restrict__ Wh2, const float* __restrict__ bh2,
                       float* __restrict__ out) {
    __shared__ float pooled[128];
    __shared__ float wsum[2];
    int g = blockIdx.x;
    int t = threadIdx.x;                  // 64 threads
    float inv = 1.0f / fmaxf(g_cnts[g], 1.0f);
    pooled[t]      = g_sums[g * HIDD + t] * inv;
    pooled[t + 64] = g_sums[g * HIDD + 64 + t] * inv;
    __syncthreads();
    float a = 0.f;
#pragma unroll 4
    for (int k = 0; k < 128; k++) a += pooled[k] * Wh1[k * 64 + t];
    a = fmaxf(a + bh1[t], 0.f) * Wh2[t];
#pragma unroll
    for (int off = 16; off >= 1; off >>= 1) a += __shfl_xor_sync(0xffffffffu, a, off);
    if ((t & 31) == 0) wsum[t >> 5] = a;
    __syncthreads();
    if (t == 0) out[g] = wsum[0] + wsum[1] + bh2[0];
}

// ---------------- launcher ---------------------------------------------------
extern "C" void kernel_launch(void* const* d_in, const int* in_sizes, int n_in,
                              void* d_out, int out_size) {
    const float* x     = (const float*)d_in[0];
    const void*  ei    = d_in[1];
    const void*  bt    = d_in[2];
    const float* W     = (const float*)d_in[3];
    const float* asrc  = (const float*)d_in[4];
    const float* adst  = (const float*)d_in[5];
    const float* bias  = (const float*)d_in[6];
    const float* gamma = (const float*)d_in[7];
    const float* beta  = (const float*)d_in[8];
    const float* bnm   = (const float*)d_in[9];
    const float* bnv   = (const float*)d_in[10];
    const float* Wh1   = (const float*)d_in[11];
    const float* bh1   = (const float*)d_in[12];
    const float* Wh2   = (const float*)d_in[13];
    const float* bh2   = (const float*)d_in[14];
    float* out = (float*)d_out;

    k_detect<<<1, 1>>>((const int*)ei);
    k_convert<<<(ET + 255) / 256, 256>>>(ei, bt);

    const int gemm_grid = (NN + 127) / 128;          // 782
    const int att_grid  = ((long long)NN * 32 + 255) / 256;   // 12500
    const int n32_grid  = (NN * 32 + 255) / 256;     // 12500
    const int e_grid    = (ET + 255) / 256;
    const int e32_grid  = (int)(((long long)ET * 32 + 255) / 256);  // 212500

    // buffer plan: layer0 reads x    -> acc bufA
    //              layer1 reads bufA -> acc bufB
    //              layer2 reads bufB -> acc bufA
    const int accsel[3] = {0, 1, 0};
    const int xsel[3]   = {-1, 0, 1};

    for (int l = 0; l < 3; l++) {
        k_gemm<<<gemm_grid, 256>>>(x, xsel[l], W + (size_t)l * HIDD * HIDD);
        k_att<<<att_grid, 256>>>(asrc + l * NHEAD * HDIM, adst + l * NHEAD * HDIM);
        k_init<<<n32_grid, 256>>>(bias + l * HIDD, accsel[l]);
        k_edge1<<<e_grid, 256>>>();
        k_edge2<<<e_grid, 256>>>();
        k_edge3<<<e32_grid, 256>>>(accsel[l]);
        k_post<<<n32_grid, 256>>>(accsel[l], gamma + l * HIDD, beta + l * HIDD,
                                  bnm + l * HIDD, bnv + l * HIDD);
    }

    k_poolinit<<<(NG * HIDD + 255) / 256, 256>>>();
    k_pool<<<POOL_BLOCKS, 128>>>(accsel[2]);
    k_head<<<NG, 64>>>(Wh1, bh1, Wh2, bh2, out);
}

// round 6
// speedup vs baseline: 1.6588x; 1.6588x over previous
#include <cuda_runtime.h>

#define NN 100000
#define EE 1600000
#define ET (EE + NN)        // 1,700,000 edges incl self loops
#define HIDD 128
#define NHEAD 4
#define HDIM 32
#define NG 128
#define NEG 0.2f
#define BNEPS 1e-5f

#define SCAN_B 512
#define NSCAN ((NN + SCAN_B - 1) / SCAN_B)   // 196

// ---------------- scratch (device globals; no dynamic allocation) ----------
__device__ float g_h[(size_t)NN * HIDD];     // per-layer transformed features
__device__ float g_bufA[(size_t)NN * HIDD];  // ping
__device__ float g_bufB[(size_t)NN * HIDD];  // pong
__device__ float g_as[NN * NHEAD];
__device__ float g_ad[NN * NHEAD];
__device__ float g_e[(size_t)ET * NHEAD];    // per-edge unnormalized probs (CSR order)
__device__ float g_den[NN * NHEAD];
__device__ int   g_csr_src[ET];
__device__ int   g_deg[NN];
__device__ int   g_ptr[NN + 1];
__device__ int   g_wptr[NN];
__device__ int   g_part[256];
__device__ int   g_poff[256];
__device__ int   g_batch[NN];
__device__ float g_sums[NG * HIDD];
__device__ float g_cnts[NG];
__device__ int   g_i64;

// ---------------- helpers ---------------------------------------------------
__device__ __forceinline__ float lrelu(float v) { return v > 0.f ? v : NEG * v; }
__device__ __forceinline__ float* accbuf(int sel) { return sel == 0 ? g_bufA : g_bufB; }
__device__ __forceinline__ float comp4(float4 v, int h) {
    return (h == 0) ? v.x : (h == 1) ? v.y : (h == 2) ? v.z : v.w;
}

// ---------------- dtype detection -------------------------------------------
__global__ void k_detect(const int* ei) {
    g_i64 = (ei[1] == 0) & (ei[3] == 0) & (ei[5] == 0) & (ei[7] == 0);
}

// zero deg + convert batch
__global__ void k_prep(const void* bt) {
    int i = blockIdx.x * blockDim.x + threadIdx.x;
    if (i >= NN) return;
    g_deg[i] = 0;
    g_batch[i] = g_i64 ? (int)((const long long*)bt)[i] : ((const int*)bt)[i];
}

__device__ __forceinline__ int edge_dst(const void* ei, int e, int f) {
    if (e >= EE) return e - EE;
    return f ? (int)((const long long*)ei)[EE + e] : ((const int*)ei)[EE + e];
}
__device__ __forceinline__ int edge_src(const void* ei, int e, int f) {
    if (e >= EE) return e - EE;
    return f ? (int)((const long long*)ei)[e] : ((const int*)ei)[e];
}

__global__ void k_hist(const void* ei) {
    int e = blockIdx.x * blockDim.x + threadIdx.x;
    if (e >= ET) return;
    atomicAdd(&g_deg[edge_dst(ei, e, g_i64)], 1);
}

__global__ void k_scan1() {
    __shared__ int sm[SCAN_B];
    int i = blockIdx.x * SCAN_B + threadIdx.x;
    int v = (i < NN) ? g_deg[i] : 0;
    sm[threadIdx.x] = v;
    __syncthreads();
    for (int off = 1; off < SCAN_B; off <<= 1) {
        int t = (threadIdx.x >= off) ? sm[threadIdx.x - off] : 0;
        __syncthreads();
        sm[threadIdx.x] += t;
        __syncthreads();
    }
    if (i < NN) g_ptr[i] = sm[threadIdx.x] - v;           // block-local exclusive
    if (threadIdx.x == SCAN_B - 1) g_part[blockIdx.x] = sm[threadIdx.x];
}

__global__ void k_scan2() {   // 1 block, 256 threads, NSCAN<=256
    __shared__ int sm[256];
    int t = threadIdx.x;
    int v = (t < NSCAN) ? g_part[t] : 0;
    sm[t] = v;
    __syncthreads();
    for (int off = 1; off < 256; off <<= 1) {
        int x = (t >= off) ? sm[t - off] : 0;
        __syncthreads();
        sm[t] += x;
        __syncthreads();
    }
    if (t < NSCAN) g_poff[t] = sm[t] - v;                 // exclusive
}

__global__ void k_scan3() {
    int i = blockIdx.x * blockDim.x + threadIdx.x;
    if (i < NN) {
        int v = g_ptr[i] + g_poff[i / SCAN_B];
        g_ptr[i] = v;
        g_wptr[i] = v;
    }
    if (i == 0) g_ptr[NN] = ET;
}

__global__ void k_scatter(const void* ei) {
    int e = blockIdx.x * blockDim.x + threadIdx.x;
    if (e >= ET) return;
    int f = g_i64;
    int d = edge_dst(ei, e, f);
    int s = edge_src(ei, e, f);
    int pos = atomicAdd(&g_wptr[d], 1);
    g_csr_src[pos] = s;
}

// ---------------- GEMM: h = X @ W  (128x128 weight) --------------------------
__global__ void k_gemm(const float* __restrict__ Xext, int xsel,
                       const float* __restrict__ W) {
    const float* X = (xsel < 0) ? Xext : (xsel == 0 ? g_bufA : g_bufB);
    __shared__ float Xs[128][17];
    __shared__ float Ws[16][128];
    int t  = threadIdx.x;            // 256 threads
    int tx = t & 15, ty = t >> 4;
    int row0 = blockIdx.x * 128;
    float acc[8][8];
#pragma unroll
    for (int i = 0; i < 8; i++)
#pragma unroll
        for (int j = 0; j < 8; j++) acc[i][j] = 0.f;

    for (int kk = 0; kk < HIDD; kk += 16) {
        int r  = t >> 1;
        int c0 = (t & 1) * 8;
        int gr = row0 + r;
        float v[8];
        if (gr < NN) {
            const float4* p = (const float4*)(X + (size_t)gr * HIDD + kk + c0);
            float4 a = p[0], b = p[1];
            v[0] = a.x; v[1] = a.y; v[2] = a.z; v[3] = a.w;
            v[4] = b.x; v[5] = b.y; v[6] = b.z; v[7] = b.w;
        } else {
#pragma unroll
            for (int i = 0; i < 8; i++) v[i] = 0.f;
        }
#pragma unroll
        for (int i = 0; i < 8; i++) Xs[r][c0 + i] = v[i];
        int wk = t >> 4;
        int wc = (t & 15) * 8;
        const float4* wp = (const float4*)(W + (size_t)(kk + wk) * HIDD + wc);
        *(float4*)&Ws[wk][wc]     = wp[0];
        *(float4*)&Ws[wk][wc + 4] = wp[1];
        __syncthreads();
#pragma unroll
        for (int k = 0; k < 16; k++) {
            float a[8], b[8];
#pragma unroll
            for (int i = 0; i < 8; i++) a[i] = Xs[ty * 8 + i][k];
#pragma unroll
            for (int j = 0; j < 8; j++) b[j] = Ws[k][tx * 8 + j];
#pragma unroll
            for (int i = 0; i < 8; i++)
#pragma unroll
                for (int j = 0; j < 8; j++) acc[i][j] += a[i] * b[j];
        }
        __syncthreads();
    }
#pragma unroll
    for (int i = 0; i < 8; i++) {
        int gr = row0 + ty * 8 + i;
        if (gr < NN) {
            float4* o = (float4*)(g_h + (size_t)gr * HIDD + tx * 8);
            o[0] = make_float4(acc[i][0], acc[i][1], acc[i][2], acc[i][3]);
            o[1] = make_float4(acc[i][4], acc[i][5], acc[i][6], acc[i][7]);
        }
    }
}

// ---------------- attention dot products a_s, a_d ---------------------------
__global__ void k_att(const float* __restrict__ asrc, const float* __restrict__ adst) {
    long long tid = (long long)blockIdx.x * blockDim.x + threadIdx.x;
    int n = (int)(tid >> 5);
    if (n >= NN) return;
    int lane = threadIdx.x & 31;
    int head = lane >> 3;
    int dsub = (lane & 7) * 4;
    float4 hv = *(const float4*)(g_h + (size_t)n * HIDD + head * HDIM + dsub);
    float4 s4 = *(const float4*)(asrc + head * HDIM + dsub);
    float4 d4 = *(const float4*)(adst + head * HDIM + dsub);
    float ps = hv.x * s4.x + hv.y * s4.y + hv.z * s4.z + hv.w * s4.w;
    float pd = hv.x * d4.x + hv.y * d4.y + hv.z * d4.z + hv.w * d4.w;
#pragma unroll
    for (int off = 4; off >= 1; off >>= 1) {
        ps += __shfl_xor_sync(0xffffffffu, ps, off);
        pd += __shfl_xor_sync(0xffffffffu, pd, off);
    }
    if ((lane & 7) == 0) {
        g_as[n * NHEAD + head] = ps;
        g_ad[n * NHEAD + head] = pd;
    }
}

// ---------------- fused segment softmax (CSR, warp per node) ----------------
__global__ void k_softmax() {
    int n = blockIdx.x * 8 + (threadIdx.x >> 5);
    if (n >= NN) return;
    int lane = threadIdx.x & 31;
    int beg = g_ptr[n], end = g_ptr[n + 1];
    float4 ad = *(const float4*)&g_ad[n * NHEAD];

    // pass 1: segment max per head
    float4 m = make_float4(-3e38f, -3e38f, -3e38f, -3e38f);
    for (int p = beg + lane; p < end; p += 32) {
        int s = g_csr_src[p];
        float4 as = *(const float4*)&g_as[s * NHEAD];
        m.x = fmaxf(m.x, lrelu(as.x + ad.x));
        m.y = fmaxf(m.y, lrelu(as.y + ad.y));
        m.z = fmaxf(m.z, lrelu(as.z + ad.z));
        m.w = fmaxf(m.w, lrelu(as.w + ad.w));
    }
#pragma unroll
    for (int off = 16; off >= 1; off >>= 1) {
        m.x = fmaxf(m.x, __shfl_xor_sync(0xffffffffu, m.x, off));
        m.y = fmaxf(m.y, __shfl_xor_sync(0xffffffffu, m.y, off));
        m.z = fmaxf(m.z, __shfl_xor_sync(0xffffffffu, m.z, off));
        m.w = fmaxf(m.w, __shfl_xor_sync(0xffffffffu, m.w, off));
    }

    // pass 2: exp + store + segment sum
    float4 sum = make_float4(0.f, 0.f, 0.f, 0.f);
    for (int p = beg + lane; p < end; p += 32) {
        int s = g_csr_src[p];
        float4 as = *(const float4*)&g_as[s * NHEAD];
        float4 pr;
        pr.x = __expf(lrelu(as.x + ad.x) - m.x);
        pr.y = __expf(lrelu(as.y + ad.y) - m.y);
        pr.z = __expf(lrelu(as.z + ad.z) - m.z);
        pr.w = __expf(lrelu(as.w + ad.w) - m.w);
        *(float4*)&g_e[(size_t)p * NHEAD] = pr;
        sum.x += pr.x; sum.y += pr.y; sum.z += pr.z; sum.w += pr.w;
    }
#pragma unroll
    for (int off = 16; off >= 1; off >>= 1) {
        sum.x += __shfl_xor_sync(0xffffffffu, sum.x, off);
        sum.y += __shfl_xor_sync(0xffffffffu, sum.y, off);
        sum.z += __shfl_xor_sync(0xffffffffu, sum.z, off);
        sum.w += __shfl_xor_sync(0xffffffffu, sum.w, off);
    }
    if (lane == 0) *(float4*)&g_den[n * NHEAD] = sum;
}

// ---------------- fused aggregation + bias + relu + BN (CSR, warp/node) -----
__global__ void k_aggr(int sel, const float* __restrict__ bias,
                       const float* __restrict__ ga, const float* __restrict__ be,
                       const float* __restrict__ mu, const float* __restrict__ va) {
    int n = blockIdx.x * 8 + (threadIdx.x >> 5);
    if (n >= NN) return;
    int lane = threadIdx.x & 31;
    int head = lane >> 3;
    int beg = g_ptr[n], end = g_ptr[n + 1];

    float4 den4 = *(const float4*)&g_den[n * NHEAD];
    float inv = __fdividef(1.f, comp4(den4, head) + 1e-16f);

    float4 acc = *(const float4*)(bias + lane * 4);

    int p = beg;
    int   s_nx  = g_csr_src[p];
    float4 pr_nx = *(const float4*)&g_e[(size_t)p * NHEAD];
    for (; p < end; p++) {
        int s = s_nx;
        float4 pr = pr_nx;
        if (p + 1 < end) {
            s_nx  = g_csr_src[p + 1];
            pr_nx = *(const float4*)&g_e[(size_t)(p + 1) * NHEAD];
        }
        float alpha = comp4(pr, head) * inv;
        float4 hv = *(const float4*)(g_h + (size_t)s * HIDD + lane * 4);
        acc.x += alpha * hv.x;
        acc.y += alpha * hv.y;
        acc.z += alpha * hv.z;
        acc.w += alpha * hv.w;
    }

    // relu + BN epilogue
    float4 g4 = *(const float4*)(ga + lane * 4);
    float4 b4 = *(const float4*)(be + lane * 4);
    float4 m4 = *(const float4*)(mu + lane * 4);
    float4 v4 = *(const float4*)(va + lane * 4);
    float4 o;
    o.x = (fmaxf(acc.x, 0.f) - m4.x) * (g4.x * rsqrtf(v4.x + BNEPS)) + b4.x;
    o.y = (fmaxf(acc.y, 0.f) - m4.y) * (g4.y * rsqrtf(v4.y + BNEPS)) + b4.y;
    o.z = (fmaxf(acc.z, 0.f) - m4.z) * (g4.z * rsqrtf(v4.z + BNEPS)) + b4.z;
    o.w = (fmaxf(acc.w, 0.f) - m4.w) * (g4.w * rsqrtf(v4.w + BNEPS)) + b4.w;
    *(float4*)(accbuf(sel) + (size_t)n * HIDD + lane * 4) = o;
}

// ---------------- pooling ----------------------------------------------------
__global__ void k_poolinit() {
    int i = blockIdx.x * blockDim.x + threadIdx.x;
    if (i < NG * HIDD) g_sums[i] = 0.f;
    if (i < NG) g_cnts[i] = 0.f;
}

#define POOL_BLOCKS 1024
__global__ void k_pool(int sel) {
    const float* X = (sel == 0) ? g_bufA : g_bufB;
    int c = threadIdx.x;                       // 128 channels
    int chunk = (NN + POOL_BLOCKS - 1) / POOL_BLOCKS;
    int n0 = blockIdx.x * chunk;
    if (n0 >= NN) return;
    int n1 = min(n0 + chunk, NN);
    int g = g_batch[n0];
    float acc = 0.f;
    int cnt = 0;
    for (int n = n0; n < n1; n++) {
        int gn = g_batch[n];
        if (gn != g) {
            atomicAdd(&g_sums[g * HIDD + c], acc);
            if (c == 0) atomicAdd(&g_cnts[g], (float)cnt);
            acc = 0.f; cnt = 0; g = gn;
        }
        acc += X[(size_t)n * HIDD + c];
        cnt++;
    }
    atomicAdd(&g_sums[g * HIDD + c], acc);
    if (c == 0) atomicAdd(&g_cnts[g], (float)cnt);
}

// ---------------- MLP head ---------------------------------------------------
__global__ void k_head(const float* __restrict__ Wh1, const float* __restrict__ bh1,
                       const float* __restrict__ Wh2, const float* __restrict__ bh2,
                       float* __restrict__ out) {
    __shared__ float pooled[128];
    __shared__ float wsum[2];
    int g = blockIdx.x;
    int t = threadIdx.x;                  // 64 threads
    float inv = 1.0f / fmaxf(g_cnts[g], 1.0f);
    pooled[t]      = g_sums[g * HIDD + t] * inv;
    pooled[t + 64] = g_sums[g * HIDD + 64 + t] * inv;
    __syncthreads();
    float a = 0.f;
#pragma unroll 4
    for (int k = 0; k < 128; k++) a += pooled[k] * Wh1[k * 64 + t];
    a = fmaxf(a + bh1[t], 0.f) * Wh2[t];
#pragma unroll
    for (int off = 16; off >= 1; off >>= 1) a += __shfl_xor_sync(0xffffffffu, a, off);
    if ((t & 31) == 0) wsum[t >> 5] = a;
    __syncthreads();
    if (t == 0) out[g] = wsum[0] + wsum[1] + bh2[0];
}

// ---------------- launcher ---------------------------------------------------
extern "C" void kernel_launch(void* const* d_in, const int* in_sizes, int n_in,
                              void* d_out, int out_size) {
    const float* x     = (const float*)d_in[0];
    const void*  ei    = d_in[1];
    const void*  bt    = d_in[2];
    const float* W     = (const float*)d_in[3];
    const float* asrc  = (const float*)d_in[4];
    const float* adst  = (const float*)d_in[5];
    const float* bias  = (const float*)d_in[6];
    const float* gamma = (const float*)d_in[7];
    const float* beta  = (const float*)d_in[8];
    const float* bnm   = (const float*)d_in[9];
    const float* bnv   = (const float*)d_in[10];
    const float* Wh1   = (const float*)d_in[11];
    const float* bh1   = (const float*)d_in[12];
    const float* Wh2   = (const float*)d_in[13];
    const float* bh2   = (const float*)d_in[14];
    float* out = (float*)d_out;

    const int e_grid    = (ET + 255) / 256;
    const int n_grid    = (NN + 255) / 256;
    const int gemm_grid = (NN + 127) / 128;
    const int att_grid  = (int)(((long long)NN * 32 + 255) / 256);
    const int wpn_grid  = (NN + 7) / 8;          // warp-per-node, 8 warps/block

    // ---- CSR build (once per launch) ----
    k_detect<<<1, 1>>>((const int*)ei);
    k_prep<<<n_grid, 256>>>(bt);
    k_hist<<<e_grid, 256>>>(ei);
    k_scan1<<<NSCAN, SCAN_B>>>();
    k_scan2<<<1, 256>>>();
    k_scan3<<<n_grid, 256>>>();
    k_scatter<<<e_grid, 256>>>(ei);

    // buffer plan: layer0 reads x    -> writes bufA
    //              layer1 reads bufA -> writes bufB
    //              layer2 reads bufB -> writes bufA
    const int accsel[3] = {0, 1, 0};
    const int xsel[3]   = {-1, 0, 1};

    for (int l = 0; l < 3; l++) {
        k_gemm<<<gemm_grid, 256>>>(x, xsel[l], W + (size_t)l * HIDD * HIDD);
        k_att<<<att_grid, 256>>>(asrc + l * NHEAD * HDIM, adst + l * NHEAD * HDIM);
        k_softmax<<<wpn_grid, 256>>>();
        k_aggr<<<wpn_grid, 256>>>(accsel[l], bias + l * HIDD,
                                  gamma + l * HIDD, beta + l * HIDD,
                                  bnm + l * HIDD, bnv + l * HIDD);
    }

    k_poolinit<<<(NG * HIDD + 255) / 256, 256>>>();
    k_pool<<<POOL_BLOCKS, 128>>>(accsel[2]);
    k_head<<<NG, 64>>>(Wh1, bh1, Wh2, bh2, out);
}

// round 10
// speedup vs baseline: 2.1741x; 1.3107x over previous
#include <cuda_runtime.h>

#define NN 100000
#define EE 1600000
#define ET (EE + NN)        // 1,700,000 edges incl self loops
#define HIDD 128
#define NHEAD 4
#define HDIM 32
#define NG 128
#define NEG 0.2f
#define BNEPS 1e-5f

#define SCAN_B 512
#define NSCAN ((NN + SCAN_B - 1) / SCAN_B)   // 196

// ---------------- scratch (device globals; no dynamic allocation) ----------
__device__ float g_h[(size_t)NN * HIDD];     // per-layer transformed features
__device__ float g_bufA[(size_t)NN * HIDD];  // ping
__device__ float g_bufB[(size_t)NN * HIDD];  // pong
__device__ float g_as[NN * NHEAD];
__device__ float g_ad[NN * NHEAD];
__device__ int   g_csr_src[ET];
__device__ int   g_deg[NN];
__device__ int   g_ptr[NN + 1];
__device__ int   g_wptr[NN];
__device__ int   g_part[256];
__device__ int   g_poff[256];
__device__ int   g_batch[NN];
__device__ float g_sums[NG * HIDD];
__device__ float g_cnts[NG];
__device__ int   g_i64;

// ---------------- helpers ---------------------------------------------------
__device__ __forceinline__ float lrelu(float v) { return v > 0.f ? v : NEG * v; }
__device__ __forceinline__ float* accbuf(int sel) { return sel == 0 ? g_bufA : g_bufB; }

__device__ __forceinline__ unsigned f2tf(float v) {
    unsigned r;
    asm("cvt.rna.tf32.f32 %0, %1;" : "=r"(r) : "f"(v));
    return r;
}

// ---------------- dtype detection -------------------------------------------
__global__ void k_detect(const int* ei) {
    g_i64 = (ei[1] == 0) & (ei[3] == 0) & (ei[5] == 0) & (ei[7] == 0);
}

__global__ void k_prep(const void* bt) {
    int i = blockIdx.x * blockDim.x + threadIdx.x;
    if (i >= NN) return;
    g_deg[i] = 0;
    g_batch[i] = g_i64 ? (int)((const long long*)bt)[i] : ((const int*)bt)[i];
}

__device__ __forceinline__ int edge_dst(const void* ei, int e, int f) {
    if (e >= EE) return e - EE;
    return f ? (int)((const long long*)ei)[EE + e] : ((const int*)ei)[EE + e];
}
__device__ __forceinline__ int edge_src(const void* ei, int e, int f) {
    if (e >= EE) return e - EE;
    return f ? (int)((const long long*)ei)[e] : ((const int*)ei)[e];
}

__global__ void k_hist(const void* ei) {
    int e = blockIdx.x * blockDim.x + threadIdx.x;
    if (e >= ET) return;
    atomicAdd(&g_deg[edge_dst(ei, e, g_i64)], 1);
}

__global__ void k_scan1() {
    __shared__ int sm[SCAN_B];
    int i = blockIdx.x * SCAN_B + threadIdx.x;
    int v = (i < NN) ? g_deg[i] : 0;
    sm[threadIdx.x] = v;
    __syncthreads();
    for (int off = 1; off < SCAN_B; off <<= 1) {
        int t = (threadIdx.x >= off) ? sm[threadIdx.x - off] : 0;
        __syncthreads();
        sm[threadIdx.x] += t;
        __syncthreads();
    }
    if (i < NN) g_ptr[i] = sm[threadIdx.x] - v;           // block-local exclusive
    if (threadIdx.x == SCAN_B - 1) g_part[blockIdx.x] = sm[threadIdx.x];
}

__global__ void k_scan2() {   // 1 block, 256 threads, NSCAN<=256
    __shared__ int sm[256];
    int t = threadIdx.x;
    int v = (t < NSCAN) ? g_part[t] : 0;
    sm[t] = v;
    __syncthreads();
    for (int off = 1; off < 256; off <<= 1) {
        int x = (t >= off) ? sm[t - off] : 0;
        __syncthreads();
        sm[t] += x;
        __syncthreads();
    }
    if (t < NSCAN) g_poff[t] = sm[t] - v;                 // exclusive
}

__global__ void k_scan3() {
    int i = blockIdx.x * blockDim.x + threadIdx.x;
    if (i < NN) {
        int v = g_ptr[i] + g_poff[i / SCAN_B];
        g_ptr[i] = v;
        g_wptr[i] = v;
    }
    if (i == 0) g_ptr[NN] = ET;
}

__global__ void k_scatter(const void* ei) {
    int e = blockIdx.x * blockDim.x + threadIdx.x;
    if (e >= ET) return;
    int f = g_i64;
    int d = edge_dst(ei, e, f);
    int s = edge_src(ei, e, f);
    int pos = atomicAdd(&g_wptr[d], 1);
    g_csr_src[pos] = s;
}

// ---------------- 3xTF32 tensor-core GEMM: h = X @ W -------------------------
// Error-compensated tf32: v = hi + lo; acc += hiA*hiB + hiA*loB + loA*hiB.
// 512 threads = 16 warps (4x4), block tile 128x128, warp tile 32x32, K chunk 16.
__global__ void __launch_bounds__(512, 2) k_gemm(const float* __restrict__ Xext, int xsel,
                                                 const float* __restrict__ W) {
    const float* X = (xsel < 0) ? Xext : (xsel == 0 ? g_bufA : g_bufB);
    __shared__ unsigned XsH[128][20], XsL[128][20];   // [m][k]
    __shared__ unsigned WsH[16][132], WsL[16][132];   // [k][n]
    int tid = threadIdx.x;
    int lane = tid & 31;
    int wid = tid >> 5;
    int m_base = (wid >> 2) * 32;
    int n_base = (wid & 3) * 32;
    int grp = lane >> 2;      // 0..7
    int tig = lane & 3;       // 0..3
    int row0 = blockIdx.x * 128;

    float c[2][4][4];
#pragma unroll
    for (int mt = 0; mt < 2; mt++)
#pragma unroll
        for (int nt = 0; nt < 4; nt++)
#pragma unroll
            for (int i = 0; i < 4; i++) c[mt][nt][i] = 0.f;

    for (int kk = 0; kk < HIDD; kk += 16) {
        // stage X tile [128 x 16]: 512 float4, one per thread
        {
            int r  = tid >> 2;
            int c4 = tid & 3;
            int gr = row0 + r;
            float4 v = make_float4(0.f, 0.f, 0.f, 0.f);
            if (gr < NN) v = *(const float4*)(X + (size_t)gr * HIDD + kk + c4 * 4);
            uint4 h4 = make_uint4(f2tf(v.x), f2tf(v.y), f2tf(v.z), f2tf(v.w));
            uint4 l4 = make_uint4(f2tf(v.x - __uint_as_float(h4.x)),
                                  f2tf(v.y - __uint_as_float(h4.y)),
                                  f2tf(v.z - __uint_as_float(h4.z)),
                                  f2tf(v.w - __uint_as_float(h4.w)));
            *(uint4*)&XsH[r][c4 * 4] = h4;
            *(uint4*)&XsL[r][c4 * 4] = l4;
        }
        // stage W tile [16 x 128]: 512 float4, one per thread
        {
            int r  = tid >> 5;               // 0..15
            int c4 = tid & 31;
            float4 v = *(const float4*)(W + (size_t)(kk + r) * HIDD + c4 * 4);
            uint4 h4 = make_uint4(f2tf(v.x), f2tf(v.y), f2tf(v.z), f2tf(v.w));
            uint4 l4 = make_uint4(f2tf(v.x - __uint_as_float(h4.x)),
                                  f2tf(v.y - __uint_as_float(h4.y)),
                                  f2tf(v.z - __uint_as_float(h4.z)),
                                  f2tf(v.w - __uint_as_float(h4.w)));
            *(uint4*)&WsH[r][c4 * 4] = h4;
            *(uint4*)&WsL[r][c4 * 4] = l4;
        }
        __syncthreads();

#pragma unroll
        for (int k8 = 0; k8 < 2; k8++) {
            int ko = k8 * 8;
            unsigned aH[2][4], aL[2][4], bH[4][2], bL[4][2];
#pragma unroll
            for (int mt = 0; mt < 2; mt++) {
                int r = m_base + mt * 16 + grp;
                aH[mt][0] = XsH[r][ko + tig];
                aH[mt][1] = XsH[r + 8][ko + tig];
                aH[mt][2] = XsH[r][ko + tig + 4];
                aH[mt][3] = XsH[r + 8][ko + tig + 4];
                aL[mt][0] = XsL[r][ko + tig];
                aL[mt][1] = XsL[r + 8][ko + tig];
                aL[mt][2] = XsL[r][ko + tig + 4];
                aL[mt][3] = XsL[r + 8][ko + tig + 4];
            }
#pragma unroll
            for (int nt = 0; nt < 4; nt++) {
                int n = n_base + nt * 8 + grp;
                bH[nt][0] = WsH[ko + tig][n];
                bH[nt][1] = WsH[ko + tig + 4][n];
                bL[nt][0] = WsL[ko + tig][n];
                bL[nt][1] = WsL[ko + tig + 4][n];
            }
#define MMA(ci, A, B)                                                          \
    asm volatile(                                                              \
        "mma.sync.aligned.m16n8k8.row.col.f32.tf32.tf32.f32 "                  \
        "{%0,%1,%2,%3}, {%4,%5,%6,%7}, {%8,%9}, {%0,%1,%2,%3};"                \
        : "+f"(ci[0]), "+f"(ci[1]), "+f"(ci[2]), "+f"(ci[3])                   \
        : "r"(A[0]), "r"(A[1]), "r"(A[2]), "r"(A[3]), "r"(B[0]), "r"(B[1]))
#pragma unroll
            for (int mt = 0; mt < 2; mt++)
#pragma unroll
                for (int nt = 0; nt < 4; nt++) {
                    MMA(c[mt][nt], aH[mt], bL[nt]);   // hi*lo
                    MMA(c[mt][nt], aL[mt], bH[nt]);   // lo*hi
                    MMA(c[mt][nt], aH[mt], bH[nt]);   // hi*hi (last: largest term)
                }
#undef MMA
        }
        __syncthreads();
    }

    // epilogue: write h
#pragma unroll
    for (int mt = 0; mt < 2; mt++) {
        int r_lo = row0 + m_base + mt * 16 + grp;
        int r_hi = r_lo + 8;
#pragma unroll
        for (int nt = 0; nt < 4; nt++) {
            int col = n_base + nt * 8 + 2 * tig;
            if (r_lo < NN)
                *(float2*)(g_h + (size_t)r_lo * HIDD + col) =
                    make_float2(c[mt][nt][0], c[mt][nt][1]);
            if (r_hi < NN)
                *(float2*)(g_h + (size_t)r_hi * HIDD + col) =
                    make_float2(c[mt][nt][2], c[mt][nt][3]);
        }
    }
}

// ---------------- attention dot products a_s, a_d ---------------------------
__global__ void k_att(const float* __restrict__ asrc, const float* __restrict__ adst) {
    long long tid = (long long)blockIdx.x * blockDim.x + threadIdx.x;
    int n = (int)(tid >> 5);
    if (n >= NN) return;
    int lane = threadIdx.x & 31;
    int head = lane >> 3;
    int dsub = (lane & 7) * 4;
    float4 hv = *(const float4*)(g_h + (size_t)n * HIDD + head * HDIM + dsub);
    float4 s4 = *(const float4*)(asrc + head * HDIM + dsub);
    float4 d4 = *(const float4*)(adst + head * HDIM + dsub);
    float ps = hv.x * s4.x + hv.y * s4.y + hv.z * s4.z + hv.w * s4.w;
    float pd = hv.x * d4.x + hv.y * d4.y + hv.z * d4.z + hv.w * d4.w;
#pragma unroll
    for (int off = 4; off >= 1; off >>= 1) {
        ps += __shfl_xor_sync(0xffffffffu, ps, off);
        pd += __shfl_xor_sync(0xffffffffu, pd, off);
    }
    if ((lane & 7) == 0) {
        g_as[n * NHEAD + head] = ps;
        g_ad[n * NHEAD + head] = pd;
    }
}

// ---------------- fused single-pass edge phase (warp per node) --------------
// out = (sum_e p_e * h[src_e]) / (sum_e p_e), p_e = exp(lrelu(as[src]+ad[dst]))
// (no max-subtraction: logits are O(+-6), exp cannot overflow; deg >= 1)
// then + bias, ReLU, BatchNorm -- all fused.
__global__ void k_edge(int sel, const float* __restrict__ bias,
                       const float* __restrict__ ga, const float* __restrict__ be,
                       const float* __restrict__ mu, const float* __restrict__ va) {
    int n = blockIdx.x * 8 + (threadIdx.x >> 5);
    if (n >= NN) return;
    int lane = threadIdx.x & 31;
    int head = lane >> 3;
    int beg = g_ptr[n], end = g_ptr[n + 1];

    float adh = g_ad[n * NHEAD + head];

    float4 acc = make_float4(0.f, 0.f, 0.f, 0.f);
    float psum = 0.f;

    int p = beg;
    int s_nx = g_csr_src[p];
    float as_nx = g_as[s_nx * NHEAD + head];
    for (; p < end; p++) {
        int s = s_nx;
        float asv = as_nx;
        if (p + 1 < end) {
            s_nx  = g_csr_src[p + 1];
            as_nx = g_as[s_nx * NHEAD + head];
        }
        float pe = __expf(lrelu(asv + adh));
        float4 hv = *(const float4*)(g_h + (size_t)s * HIDD + lane * 4);
        acc.x += pe * hv.x;
        acc.y += pe * hv.y;
        acc.z += pe * hv.z;
        acc.w += pe * hv.w;
        psum += pe;
    }

    float inv = __fdividef(1.f, psum + 1e-16f);
    float4 b0 = *(const float4*)(bias + lane * 4);
    float4 g4 = *(const float4*)(ga + lane * 4);
    float4 b4 = *(const float4*)(be + lane * 4);
    float4 m4 = *(const float4*)(mu + lane * 4);
    float4 v4 = *(const float4*)(va + lane * 4);
    float4 o;
    o.x = (fmaxf(acc.x * inv + b0.x, 0.f) - m4.x) * (g4.x * rsqrtf(v4.x + BNEPS)) + b4.x;
    o.y = (fmaxf(acc.y * inv + b0.y, 0.f) - m4.y) * (g4.y * rsqrtf(v4.y + BNEPS)) + b4.y;
    o.z = (fmaxf(acc.z * inv + b0.z, 0.f) - m4.z) * (g4.z * rsqrtf(v4.z + BNEPS)) + b4.z;
    o.w = (fmaxf(acc.w * inv + b0.w, 0.f) - m4.w) * (g4.w * rsqrtf(v4.w + BNEPS)) + b4.w;
    *(float4*)(accbuf(sel) + (size_t)n * HIDD + lane * 4) = o;
}

// ---------------- pooling ----------------------------------------------------
__global__ void k_poolinit() {
    int i = blockIdx.x * blockDim.x + threadIdx.x;
    if (i < NG * HIDD) g_sums[i] = 0.f;
    if (i < NG) g_cnts[i] = 0.f;
}

#define POOL_BLOCKS 1024
__global__ void k_pool(int sel) {
    const float* X = (sel == 0) ? g_bufA : g_bufB;
    int c = threadIdx.x;                       // 128 channels
    int chunk = (NN + POOL_BLOCKS - 1) / POOL_BLOCKS;
    int n0 = blockIdx.x * chunk;
    if (n0 >= NN) return;
    int n1 = min(n0 + chunk, NN);
    int g = g_batch[n0];
    float acc = 0.f;
    int cnt = 0;
    for (int n = n0; n < n1; n++) {
        int gn = g_batch[n];
        if (gn != g) {
            atomicAdd(&g_sums[g * HIDD + c], acc);
            if (c == 0) atomicAdd(&g_cnts[g], (float)cnt);
            acc = 0.f; cnt = 0; g = gn;
        }
        acc += X[(size_t)n * HIDD + c];
        cnt++;
    }
    atomicAdd(&g_sums[g * HIDD + c], acc);
    if (c == 0) atomicAdd(&g_cnts[g], (float)cnt);
}

// ---------------- MLP head ---------------------------------------------------
__global__ void k_head(const float* __restrict__ Wh1, const float* __restrict__ bh1,
                       const float* __restrict__ Wh2, const float* __restrict__ bh2,
                       float* __restrict__ out) {
    __shared__ float pooled[128];
    __shared__ float wsum[2];
    int g = blockIdx.x;
    int t = threadIdx.x;                  // 64 threads
    float inv = 1.0f / fmaxf(g_cnts[g], 1.0f);
    pooled[t]      = g_sums[g * HIDD + t] * inv;
    pooled[t + 64] = g_sums[g * HIDD + 64 + t] * inv;
    __syncthreads();
    float a = 0.f;
#pragma unroll 4
    for (int k = 0; k < 128; k++) a += pooled[k] * Wh1[k * 64 + t];
    a = fmaxf(a + bh1[t], 0.f) * Wh2[t];
#pragma unroll
    for (int off = 16; off >= 1; off >>= 1) a += __shfl_xor_sync(0xffffffffu, a, off);
    if ((t & 31) == 0) wsum[t >> 5] = a;
    __syncthreads();
    if (t == 0) out[g] = wsum[0] + wsum[1] + bh2[0];
}

// ---------------- launcher ---------------------------------------------------
extern "C" void kernel_launch(void* const* d_in, const int* in_sizes, int n_in,
                              void* d_out, int out_size) {
    const float* x     = (const float*)d_in[0];
    const void*  ei    = d_in[1];
    const void*  bt    = d_in[2];
    const float* W     = (const float*)d_in[3];
    const float* asrc  = (const float*)d_in[4];
    const float* adst  = (const float*)d_in[5];
    const float* bias  = (const float*)d_in[6];
    const float* gamma = (const float*)d_in[7];
    const float* beta  = (const float*)d_in[8];
    const float* bnm   = (const float*)d_in[9];
    const float* bnv   = (const float*)d_in[10];
    const float* Wh1   = (const float*)d_in[11];
    const float* bh1   = (const float*)d_in[12];
    const float* Wh2   = (const float*)d_in[13];
    const float* bh2   = (const float*)d_in[14];
    float* out = (float*)d_out;

    const int e_grid    = (ET + 255) / 256;
    const int n_grid    = (NN + 255) / 256;
    const int gemm_grid = (NN + 127) / 128;          // 782
    const int att_grid  = (int)(((long long)NN * 32 + 255) / 256);
    const int wpn_grid  = (NN + 7) / 8;              // warp-per-node

    // ---- CSR build (once per launch) ----
    k_detect<<<1, 1>>>((const int*)ei);
    k_prep<<<n_grid, 256>>>(bt);
    k_hist<<<e_grid, 256>>>(ei);
    k_scan1<<<NSCAN, SCAN_B>>>();
    k_scan2<<<1, 256>>>();
    k_scan3<<<n_grid, 256>>>();
    k_scatter<<<e_grid, 256>>>(ei);

    // buffer plan: layer0 reads x -> bufA; layer1 bufA -> bufB; layer2 bufB -> bufA
    const int accsel[3] = {0, 1, 0};
    const int xsel[3]   = {-1, 0, 1};

    for (int l = 0; l < 3; l++) {
        k_gemm<<<gemm_grid, 512>>>(x, xsel[l], W + (size_t)l * HIDD * HIDD);
        k_att<<<att_grid, 256>>>(asrc + l * NHEAD * HDIM, adst + l * NHEAD * HDIM);
        k_edge<<<wpn_grid, 256>>>(accsel[l], bias + l * HIDD,
                                  gamma + l * HIDD, beta + l * HIDD,
                                  bnm + l * HIDD, bnv + l * HIDD);
    }

    k_poolinit<<<(NG * HIDD + 255) / 256, 256>>>();
    k_pool<<<POOL_BLOCKS, 128>>>(accsel[2]);
    k_head<<<NG, 64>>>(Wh1, bh1, Wh2, bh2, out);
}

// round 13
// speedup vs baseline: 2.3364x; 1.0746x over previous
#include <cuda_runtime.h>
#include <cuda_bf16.h>

#define NN 100000
#define EE 1600000
#define ET (EE + NN)        // 1,700,000 edges incl self loops
#define HIDD 128
#define NHEAD 4
#define HDIM 32
#define NG 128
#define NEG 0.2f
#define BNEPS 1e-5f

#define SCAN_B 512
#define NSCAN ((NN + SCAN_B - 1) / SCAN_B)   // 196

// ---------------- scratch (device globals; no dynamic allocation) ----------
__device__ __nv_bfloat16 g_hb[(size_t)NN * HIDD];  // transformed features (bf16 messages)
__device__ float g_bufA[(size_t)NN * HIDD];  // ping
__device__ float g_bufB[(size_t)NN * HIDD];  // pong
__device__ float g_as[NN * NHEAD];
__device__ float g_ad[NN * NHEAD];
__device__ int   g_csr_src[ET];
__device__ int   g_deg[NN];
__device__ int   g_ptr[NN + 1];
__device__ int   g_wptr[NN];
__device__ int   g_part[256];
__device__ int   g_poff[256];
__device__ int   g_batch[NN];
__device__ float g_sums[NG * HIDD];
__device__ float g_cnts[NG];
__device__ int   g_i64;

// ---------------- helpers ---------------------------------------------------
__device__ __forceinline__ float lrelu(float v) { return v > 0.f ? v : NEG * v; }
__device__ __forceinline__ float* accbuf(int sel) { return sel == 0 ? g_bufA : g_bufB; }

__device__ __forceinline__ unsigned f2tf(float v) {
    unsigned r;
    asm("cvt.rna.tf32.f32 %0, %1;" : "=r"(r) : "f"(v));
    return r;
}

// ---------------- dtype detection -------------------------------------------
__global__ void k_detect(const int* ei) {
    g_i64 = (ei[1] == 0) & (ei[3] == 0) & (ei[5] == 0) & (ei[7] == 0);
}

__global__ void k_prep(const void* bt) {
    int i = blockIdx.x * blockDim.x + threadIdx.x;
    if (i >= NN) return;
    g_deg[i] = 0;
    g_batch[i] = g_i64 ? (int)((const long long*)bt)[i] : ((const int*)bt)[i];
}

__device__ __forceinline__ int edge_dst(const void* ei, int e, int f) {
    if (e >= EE) return e - EE;
    return f ? (int)((const long long*)ei)[EE + e] : ((const int*)ei)[EE + e];
}
__device__ __forceinline__ int edge_src(const void* ei, int e, int f) {
    if (e >= EE) return e - EE;
    return f ? (int)((const long long*)ei)[e] : ((const int*)ei)[e];
}

__global__ void k_hist(const void* ei) {
    int e = blockIdx.x * blockDim.x + threadIdx.x;
    if (e >= ET) return;
    atomicAdd(&g_deg[edge_dst(ei, e, g_i64)], 1);
}

__global__ void k_scan1() {
    __shared__ int sm[SCAN_B];
    int i = blockIdx.x * SCAN_B + threadIdx.x;
    int v = (i < NN) ? g_deg[i] : 0;
    sm[threadIdx.x] = v;
    __syncthreads();
    for (int off = 1; off < SCAN_B; off <<= 1) {
        int t = (threadIdx.x >= off) ? sm[threadIdx.x - off] : 0;
        __syncthreads();
        sm[threadIdx.x] += t;
        __syncthreads();
    }
    if (i < NN) g_ptr[i] = sm[threadIdx.x] - v;           // block-local exclusive
    if (threadIdx.x == SCAN_B - 1) g_part[blockIdx.x] = sm[threadIdx.x];
}

__global__ void k_scan2() {   // 1 block, 256 threads, NSCAN<=256
    __shared__ int sm[256];
    int t = threadIdx.x;
    int v = (t < NSCAN) ? g_part[t] : 0;
    sm[t] = v;
    __syncthreads();
    for (int off = 1; off < 256; off <<= 1) {
        int x = (t >= off) ? sm[t - off] : 0;
        __syncthreads();
        sm[t] += x;
        __syncthreads();
    }
    if (t < NSCAN) g_poff[t] = sm[t] - v;                 // exclusive
}

__global__ void k_scan3() {
    int i = blockIdx.x * blockDim.x + threadIdx.x;
    if (i < NN) {
        int v = g_ptr[i] + g_poff[i / SCAN_B];
        g_ptr[i] = v;
        g_wptr[i] = v;
    }
    if (i == 0) g_ptr[NN] = ET;
}

__global__ void k_scatter(const void* ei) {
    int e = blockIdx.x * blockDim.x + threadIdx.x;
    if (e >= ET) return;
    int f = g_i64;
    int d = edge_dst(ei, e, f);
    int s = edge_src(ei, e, f);
    int pos = atomicAdd(&g_wptr[d], 1);
    g_csr_src[pos] = s;
}

// ---------------- 3xTF32 tensor-core GEMM + fused attention epilogue --------
// h = X @ W (error-compensated tf32), writes bf16 h + per-head attention dots.
// Warp tile 32x32; the 32-col warp tile == one head (HDIM=32), so each warp
// computes complete a_s/a_d row dots from its fp32 accumulators.
__global__ void __launch_bounds__(512, 2) k_gemm(const float* __restrict__ Xext, int xsel,
                                                 const float* __restrict__ W,
                                                 const float* __restrict__ asrc,
                                                 const float* __restrict__ adst) {
    const float* X = (xsel < 0) ? Xext : (xsel == 0 ? g_bufA : g_bufB);
    __shared__ unsigned XsH[128][20], XsL[128][20];   // [m][k]
    __shared__ unsigned WsH[16][132], WsL[16][132];   // [k][n]
    int tid = threadIdx.x;
    int lane = tid & 31;
    int wid = tid >> 5;
    int m_base = (wid >> 2) * 32;
    int n_base = (wid & 3) * 32;      // == head * HDIM
    int head = wid & 3;
    int grp = lane >> 2;      // 0..7
    int tig = lane & 3;       // 0..3
    int row0 = blockIdx.x * 128;

    float c[2][4][4];
#pragma unroll
    for (int mt = 0; mt < 2; mt++)
#pragma unroll
        for (int nt = 0; nt < 4; nt++)
#pragma unroll
            for (int i = 0; i < 4; i++) c[mt][nt][i] = 0.f;

    for (int kk = 0; kk < HIDD; kk += 16) {
        // stage X tile [128 x 16]: 512 float4, one per thread
        {
            int r  = tid >> 2;
            int c4 = tid & 3;
            int gr = row0 + r;
            float4 v = make_float4(0.f, 0.f, 0.f, 0.f);
            if (gr < NN) v = *(const float4*)(X + (size_t)gr * HIDD + kk + c4 * 4);
            uint4 h4 = make_uint4(f2tf(v.x), f2tf(v.y), f2tf(v.z), f2tf(v.w));
            uint4 l4 = make_uint4(f2tf(v.x - __uint_as_float(h4.x)),
                                  f2tf(v.y - __uint_as_float(h4.y)),
                                  f2tf(v.z - __uint_as_float(h4.z)),
                                  f2tf(v.w - __uint_as_float(h4.w)));
            *(uint4*)&XsH[r][c4 * 4] = h4;
            *(uint4*)&XsL[r][c4 * 4] = l4;
        }
        // stage W tile [16 x 128]: 512 float4, one per thread
        {
            int r  = tid >> 5;               // 0..15
            int c4 = tid & 31;
            float4 v = *(const float4*)(W + (size_t)(kk + r) * HIDD + c4 * 4);
            uint4 h4 = make_uint4(f2tf(v.x), f2tf(v.y), f2tf(v.z), f2tf(v.w));
            uint4 l4 = make_uint4(f2tf(v.x - __uint_as_float(h4.x)),
                                  f2tf(v.y - __uint_as_float(h4.y)),
                                  f2tf(v.z - __uint_as_float(h4.z)),
                                  f2tf(v.w - __uint_as_float(h4.w)));
            *(uint4*)&WsH[r][c4 * 4] = h4;
            *(uint4*)&WsL[r][c4 * 4] = l4;
        }
        __syncthreads();

#pragma unroll
        for (int k8 = 0; k8 < 2; k8++) {
            int ko = k8 * 8;
            unsigned aH[2][4], aL[2][4], bH[4][2], bL[4][2];
#pragma unroll
            for (int mt = 0; mt < 2; mt++) {
                int r = m_base + mt * 16 + grp;
                aH[mt][0] = XsH[r][ko + tig];
                aH[mt][1] = XsH[r + 8][ko + tig];
                aH[mt][2] = XsH[r][ko + tig + 4];
                aH[mt][3] = XsH[r + 8][ko + tig + 4];
                aL[mt][0] = XsL[r][ko + tig];
                aL[mt][1] = XsL[r + 8][ko + tig];
                aL[mt][2] = XsL[r][ko + tig + 4];
                aL[mt][3] = XsL[r + 8][ko + tig + 4];
            }
#pragma unroll
            for (int nt = 0; nt < 4; nt++) {
                int n = n_base + nt * 8 + grp;
                bH[nt][0] = WsH[ko + tig][n];
                bH[nt][1] = WsH[ko + tig + 4][n];
                bL[nt][0] = WsL[ko + tig][n];
                bL[nt][1] = WsL[ko + tig + 4][n];
            }
#define MMA(ci, A, B)                                                          \
    asm volatile(                                                              \
        "mma.sync.aligned.m16n8k8.row.col.f32.tf32.tf32.f32 "                  \
        "{%0,%1,%2,%3}, {%4,%5,%6,%7}, {%8,%9}, {%0,%1,%2,%3};"                \
        : "+f"(ci[0]), "+f"(ci[1]), "+f"(ci[2]), "+f"(ci[3])                   \
        : "r"(A[0]), "r"(A[1]), "r"(A[2]), "r"(A[3]), "r"(B[0]), "r"(B[1]))
#pragma unroll
            for (int mt = 0; mt < 2; mt++)
#pragma unroll
                for (int nt = 0; nt < 4; nt++) {
                    MMA(c[mt][nt], aH[mt], bL[nt]);   // hi*lo
                    MMA(c[mt][nt], aL[mt], bH[nt]);   // lo*hi
                    MMA(c[mt][nt], aH[mt], bH[nt]);   // hi*hi (last: largest term)
                }
#undef MMA
        }
        __syncthreads();
    }

    // ---- epilogue 1: bf16 h ----
#pragma unroll
    for (int mt = 0; mt < 2; mt++) {
        int r_lo = row0 + m_base + mt * 16 + grp;
        int r_hi = r_lo + 8;
#pragma unroll
        for (int nt = 0; nt < 4; nt++) {
            int col = n_base + nt * 8 + 2 * tig;
            if (r_lo < NN)
                *(__nv_bfloat162*)(g_hb + (size_t)r_lo * HIDD + col) =
                    __float22bfloat162_rn(make_float2(c[mt][nt][0], c[mt][nt][1]));
            if (r_hi < NN)
                *(__nv_bfloat162*)(g_hb + (size_t)r_hi * HIDD + col) =
                    __float22bfloat162_rn(make_float2(c[mt][nt][2], c[mt][nt][3]));
        }
    }

    // ---- epilogue 2: fused attention dots (exact fp32) ----
#pragma unroll
    for (int mt = 0; mt < 2; mt++) {
        float sl = 0.f, dl = 0.f, sh = 0.f, dh = 0.f;
#pragma unroll
        for (int nt = 0; nt < 4; nt++) {
            int col = n_base + nt * 8 + 2 * tig;
            float a0 = asrc[col], a1 = asrc[col + 1];
            float d0 = adst[col], d1 = adst[col + 1];
            sl += c[mt][nt][0] * a0 + c[mt][nt][1] * a1;
            dl += c[mt][nt][0] * d0 + c[mt][nt][1] * d1;
            sh += c[mt][nt][2] * a0 + c[mt][nt][3] * a1;
            dh += c[mt][nt][2] * d0 + c[mt][nt][3] * d1;
        }
#pragma unroll
        for (int off = 1; off <= 2; off <<= 1) {     // reduce over tig group
            sl += __shfl_xor_sync(0xffffffffu, sl, off);
            dl += __shfl_xor_sync(0xffffffffu, dl, off);
            sh += __shfl_xor_sync(0xffffffffu, sh, off);
            dh += __shfl_xor_sync(0xffffffffu, dh, off);
        }
        int r_lo = row0 + m_base + mt * 16 + grp;
        if (tig == 0) {
            if (r_lo < NN) {
                g_as[r_lo * NHEAD + head] = sl;
                g_ad[r_lo * NHEAD + head] = dl;
            }
            if (r_lo + 8 < NN) {
                g_as[(r_lo + 8) * NHEAD + head] = sh;
                g_ad[(r_lo + 8) * NHEAD + head] = dh;
            }
        }
    }
}

// ---------------- fused single-pass edge phase (warp per node) --------------
// out = (sum_e p_e * h[src_e]) / (sum_e p_e), p_e = exp(lrelu(as[src]+ad[dst]))
// messages gathered in bf16 (halves L2 traffic); logits exact fp32.
__global__ void k_edge(int sel, const float* __restrict__ bias,
                       const float* __restrict__ ga, const float* __restrict__ be,
                       const float* __restrict__ mu, const float* __restrict__ va) {
    int n = blockIdx.x * 8 + (threadIdx.x >> 5);
    if (n >= NN) return;
    int lane = threadIdx.x & 31;
    int head = lane >> 3;
    int beg = g_ptr[n], end = g_ptr[n + 1];

    float adh = g_ad[n * NHEAD + head];

    float4 acc = make_float4(0.f, 0.f, 0.f, 0.f);
    float psum = 0.f;

    int p = beg;
    int s_nx = g_csr_src[p];
    float as_nx = g_as[s_nx * NHEAD + head];
    for (; p < end; p++) {
        int s = s_nx;
        float asv = as_nx;
        if (p + 1 < end) {
            s_nx  = g_csr_src[p + 1];
            as_nx = g_as[s_nx * NHEAD + head];
        }
        float pe = __expf(lrelu(asv + adh));
        uint2 u = *(const uint2*)(g_hb + (size_t)s * HIDD + lane * 4);
        float2 f0 = __bfloat1622float2(*reinterpret_cast<__nv_bfloat162*>(&u.x));
        float2 f1 = __bfloat1622float2(*reinterpret_cast<__nv_bfloat162*>(&u.y));
        acc.x += pe * f0.x;
        acc.y += pe * f0.y;
        acc.z += pe * f1.x;
        acc.w += pe * f1.y;
        psum += pe;
    }

    float inv = __fdividef(1.f, psum + 1e-16f);
    float4 b0 = *(const float4*)(bias + lane * 4);
    float4 g4 = *(const float4*)(ga + lane * 4);
    float4 b4 = *(const float4*)(be + lane * 4);
    float4 m4 = *(const float4*)(mu + lane * 4);
    float4 v4 = *(const float4*)(va + lane * 4);
    float4 o;
    o.x = (fmaxf(acc.x * inv + b0.x, 0.f) - m4.x) * (g4.x * rsqrtf(v4.x + BNEPS)) + b4.x;
    o.y = (fmaxf(acc.y * inv + b0.y, 0.f) - m4.y) * (g4.y * rsqrtf(v4.y + BNEPS)) + b4.y;
    o.z = (fmaxf(acc.z * inv + b0.z, 0.f) - m4.z) * (g4.z * rsqrtf(v4.z + BNEPS)) + b4.z;
    o.w = (fmaxf(acc.w * inv + b0.w, 0.f) - m4.w) * (g4.w * rsqrtf(v4.w + BNEPS)) + b4.w;
    *(float4*)(accbuf(sel) + (size_t)n * HIDD + lane * 4) = o;
}

// ---------------- pooling ----------------------------------------------------
__global__ void k_poolinit() {
    int i = blockIdx.x * blockDim.x + threadIdx.x;
    if (i < NG * HIDD) g_sums[i] = 0.f;
    if (i < NG) g_cnts[i] = 0.f;
}

#define POOL_BLOCKS 1024
__global__ void k_pool(int sel) {
    const float* X = (sel == 0) ? g_bufA : g_bufB;
    int c = threadIdx.x;                       // 128 channels
    int chunk = (NN + POOL_BLOCKS - 1) / POOL_BLOCKS;
    int n0 = blockIdx.x * chunk;
    if (n0 >= NN) return;
    int n1 = min(n0 + chunk, NN);
    int g = g_batch[n0];
    float acc = 0.f;
    int cnt = 0;
    for (int n = n0; n < n1; n++) {
        int gn = g_batch[n];
        if (gn != g) {
            atomicAdd(&g_sums[g * HIDD + c], acc);
            if (c == 0) atomicAdd(&g_cnts[g], (float)cnt);
            acc = 0.f; cnt = 0; g = gn;
        }
        acc += X[(size_t)n * HIDD + c];
        cnt++;
    }
    atomicAdd(&g_sums[g * HIDD + c], acc);
    if (c == 0) atomicAdd(&g_cnts[g], (float)cnt);
}

// ---------------- MLP head ---------------------------------------------------
__global__ void k_head(const float* __restrict__ Wh1, const float* __restrict__ bh1,
                       const float* __restrict__ Wh2, const float* __restrict__ bh2,
                       float* __restrict__ out) {
    __shared__ float pooled[128];
    __shared__ float wsum[2];
    int g = blockIdx.x;
    int t = threadIdx.x;                  // 64 threads
    float inv = 1.0f / fmaxf(g_cnts[g], 1.0f);
    pooled[t]      = g_sums[g * HIDD + t] * inv;
    pooled[t + 64] = g_sums[g * HIDD + 64 + t] * inv;
    __syncthreads();
    float a = 0.f;
#pragma unroll 4
    for (int k = 0; k < 128; k++) a += pooled[k] * Wh1[k * 64 + t];
    a = fmaxf(a + bh1[t], 0.f) * Wh2[t];
#pragma unroll
    for (int off = 16; off >= 1; off >>= 1) a += __shfl_xor_sync(0xffffffffu, a, off);
    if ((t & 31) == 0) wsum[t >> 5] = a;
    __syncthreads();
    if (t == 0) out[g] = wsum[0] + wsum[1] + bh2[0];
}

// ---------------- launcher ---------------------------------------------------
extern "C" void kernel_launch(void* const* d_in, const int* in_sizes, int n_in,
                              void* d_out, int out_size) {
    const float* x     = (const float*)d_in[0];
    const void*  ei    = d_in[1];
    const void*  bt    = d_in[2];
    const float* W     = (const float*)d_in[3];
    const float* asrc  = (const float*)d_in[4];
    const float* adst  = (const float*)d_in[5];
    const float* bias  = (const float*)d_in[6];
    const float* gamma = (const float*)d_in[7];
    const float* beta  = (const float*)d_in[8];
    const float* bnm   = (const float*)d_in[9];
    const float* bnv   = (const float*)d_in[10];
    const float* Wh1   = (const float*)d_in[11];
    const float* bh1   = (const float*)d_in[12];
    const float* Wh2   = (const float*)d_in[13];
    const float* bh2   = (const float*)d_in[14];
    float* out = (float*)d_out;

    const int e_grid    = (ET + 255) / 256;
    const int n_grid    = (NN + 255) / 256;
    const int gemm_grid = (NN + 127) / 128;          // 782
    const int wpn_grid  = (NN + 7) / 8;              // warp-per-node

    // ---- CSR build (once per launch) ----
    k_detect<<<1, 1>>>((const int*)ei);
    k_prep<<<n_grid, 256>>>(bt);
    k_hist<<<e_grid, 256>>>(ei);
    k_scan1<<<NSCAN, SCAN_B>>>();
    k_scan2<<<1, 256>>>();
    k_scan3<<<n_grid, 256>>>();
    k_scatter<<<e_grid, 256>>>(ei);

    // buffer plan: layer0 reads x -> bufA; layer1 bufA -> bufB; layer2 bufB -> bufA
    const int accsel[3] = {0, 1, 0};
    const int xsel[3]   = {-1, 0, 1};

    for (int l = 0; l < 3; l++) {
        k_gemm<<<gemm_grid, 512>>>(x, xsel[l], W + (size_t)l * HIDD * HIDD,
                                   asrc + l * NHEAD * HDIM, adst + l * NHEAD * HDIM);
        k_edge<<<wpn_grid, 256>>>(accsel[l], bias + l * HIDD,
                                  gamma + l * HIDD, beta + l * HIDD,
                                  bnm + l * HIDD, bnv + l * HIDD);
    }

    k_poolinit<<<(NG * HIDD + 255) / 256, 256>>>();
    k_pool<<<POOL_BLOCKS, 128>>>(accsel[2]);
    k_head<<<NG, 64>>>(Wh1, bh1, Wh2, bh2, out);
}

// round 15
// speedup vs baseline: 2.3470x; 1.0045x over previous
#include <cuda_runtime.h>
#include <cuda_bf16.h>

#define NN 100000
#define EE 1600000
#define ET (EE + NN)        // 1,700,000 edges incl self loops
#define HIDD 128
#define NHEAD 4
#define HDIM 32
#define NG 128
#define NEG 0.2f
#define BNEPS 1e-5f

#define SCAN_B 512
#define NSCAN ((NN + SCAN_B - 1) / SCAN_B)   // 196

// ---------------- scratch (device globals; no dynamic allocation) ----------
__device__ __nv_bfloat16 g_hb[(size_t)NN * HIDD];  // transformed features (bf16 messages)
__device__ float g_bufA[(size_t)NN * HIDD];  // ping
__device__ float g_bufB[(size_t)NN * HIDD];  // pong
__device__ float g_as[NN * NHEAD];
__device__ float g_ad[NN * NHEAD];
__device__ int   g_csr_src[ET];
__device__ int   g_deg[NN];
__device__ int   g_ptr[NN + 1];
__device__ int   g_wptr[NN];
__device__ int   g_part[256];
__device__ int   g_poff[256];
__device__ int   g_batch[NN];
__device__ float g_sums[NG * HIDD];
__device__ float g_cnts[NG];
__device__ int   g_i64;

// ---------------- helpers ---------------------------------------------------
__device__ __forceinline__ float lrelu(float v) { return v > 0.f ? v : NEG * v; }
__device__ __forceinline__ float* accbuf(int sel) { return sel == 0 ? g_bufA : g_bufB; }

__device__ __forceinline__ unsigned f2tf(float v) {
    unsigned r;
    asm("cvt.rna.tf32.f32 %0, %1;" : "=r"(r) : "f"(v));
    return r;
}

// ---------------- dtype detection + pool zero --------------------------------
__global__ void k_detect(const int* ei) {
    int t = threadIdx.x;      // 128 threads
    if (t == 0)
        g_i64 = (ei[1] == 0) & (ei[3] == 0) & (ei[5] == 0) & (ei[7] == 0);
    g_cnts[t] = 0.f;
    for (int i = t; i < NG * HIDD; i += 128) g_sums[i] = 0.f;
}

__global__ void k_prep(const void* bt) {
    int i = blockIdx.x * blockDim.x + threadIdx.x;
    if (i >= NN) return;
    g_deg[i] = 0;
    int b = g_i64 ? (int)((const long long*)bt)[i] : ((const int*)bt)[i];
    g_batch[i] = b;
    // warp-aggregated graph node counts (batch is sorted -> few distinct b/warp)
    unsigned m = __match_any_sync(__activemask(), b);
    if (((m >> (threadIdx.x & 31)) & 1) && ((threadIdx.x & 31) == (__ffs(m) - 1)))
        atomicAdd(&g_cnts[b], (float)__popc(m));
}

__device__ __forceinline__ int edge_dst(const void* ei, int e, int f) {
    if (e >= EE) return e - EE;
    return f ? (int)((const long long*)ei)[EE + e] : ((const int*)ei)[EE + e];
}
__device__ __forceinline__ int edge_src(const void* ei, int e, int f) {
    if (e >= EE) return e - EE;
    return f ? (int)((const long long*)ei)[e] : ((const int*)ei)[e];
}

__global__ void k_hist(const void* ei) {
    int e = blockIdx.x * blockDim.x + threadIdx.x;
    if (e >= ET) return;
    atomicAdd(&g_deg[edge_dst(ei, e, g_i64)], 1);
}

__global__ void k_scan1() {
    __shared__ int sm[SCAN_B];
    int i = blockIdx.x * SCAN_B + threadIdx.x;
    int v = (i < NN) ? g_deg[i] : 0;
    sm[threadIdx.x] = v;
    __syncthreads();
    for (int off = 1; off < SCAN_B; off <<= 1) {
        int t = (threadIdx.x >= off) ? sm[threadIdx.x - off] : 0;
        __syncthreads();
        sm[threadIdx.x] += t;
        __syncthreads();
    }
    if (i < NN) g_ptr[i] = sm[threadIdx.x] - v;           // block-local exclusive
    if (threadIdx.x == SCAN_B - 1) g_part[blockIdx.x] = sm[threadIdx.x];
}

__global__ void k_scan2() {   // 1 block, 256 threads, NSCAN<=256
    __shared__ int sm[256];
    int t = threadIdx.x;
    int v = (t < NSCAN) ? g_part[t] : 0;
    sm[t] = v;
    __syncthreads();
    for (int off = 1; off < 256; off <<= 1) {
        int x = (t >= off) ? sm[t - off] : 0;
        __syncthreads();
        sm[t] += x;
        __syncthreads();
    }
    if (t < NSCAN) g_poff[t] = sm[t] - v;                 // exclusive
}

__global__ void k_scan3() {
    int i = blockIdx.x * blockDim.x + threadIdx.x;
    if (i < NN) {
        int v = g_ptr[i] + g_poff[i / SCAN_B];
        g_ptr[i] = v;
        g_wptr[i] = v;
    }
    if (i == 0) g_ptr[NN] = ET;
}

__global__ void k_scatter(const void* ei) {
    int e = blockIdx.x * blockDim.x + threadIdx.x;
    if (e >= ET) return;
    int f = g_i64;
    int d = edge_dst(ei, e, f);
    int s = edge_src(ei, e, f);
    int pos = atomicAdd(&g_wptr[d], 1);
    g_csr_src[pos] = s;
}

// ---------------- 3xTF32 tensor-core GEMM + fused attention epilogue --------
__global__ void __launch_bounds__(512, 2) k_gemm(const float* __restrict__ Xext, int xsel,
                                                 const float* __restrict__ W,
                                                 const float* __restrict__ asrc,
                                                 const float* __restrict__ adst) {
    const float* X = (xsel < 0) ? Xext : (xsel == 0 ? g_bufA : g_bufB);
    __shared__ unsigned XsH[128][20], XsL[128][20];   // [m][k]
    __shared__ unsigned WsH[16][132], WsL[16][132];   // [k][n]
    int tid = threadIdx.x;
    int lane = tid & 31;
    int wid = tid >> 5;
    int m_base = (wid >> 2) * 32;
    int n_base = (wid & 3) * 32;      // == head * HDIM
    int head = wid & 3;
    int grp = lane >> 2;      // 0..7
    int tig = lane & 3;       // 0..3
    int row0 = blockIdx.x * 128;

    float c[2][4][4];
#pragma unroll
    for (int mt = 0; mt < 2; mt++)
#pragma unroll
        for (int nt = 0; nt < 4; nt++)
#pragma unroll
            for (int i = 0; i < 4; i++) c[mt][nt][i] = 0.f;

    for (int kk = 0; kk < HIDD; kk += 16) {
        {
            int r  = tid >> 2;
            int c4 = tid & 3;
            int gr = row0 + r;
            float4 v = make_float4(0.f, 0.f, 0.f, 0.f);
            if (gr < NN) v = *(const float4*)(X + (size_t)gr * HIDD + kk + c4 * 4);
            uint4 h4 = make_uint4(f2tf(v.x), f2tf(v.y), f2tf(v.z), f2tf(v.w));
            uint4 l4 = make_uint4(f2tf(v.x - __uint_as_float(h4.x)),
                                  f2tf(v.y - __uint_as_float(h4.y)),
                                  f2tf(v.z - __uint_as_float(h4.z)),
                                  f2tf(v.w - __uint_as_float(h4.w)));
            *(uint4*)&XsH[r][c4 * 4] = h4;
            *(uint4*)&XsL[r][c4 * 4] = l4;
        }
        {
            int r  = tid >> 5;               // 0..15
            int c4 = tid & 31;
            float4 v = *(const float4*)(W + (size_t)(kk + r) * HIDD + c4 * 4);
            uint4 h4 = make_uint4(f2tf(v.x), f2tf(v.y), f2tf(v.z), f2tf(v.w));
            uint4 l4 = make_uint4(f2tf(v.x - __uint_as_float(h4.x)),
                                  f2tf(v.y - __uint_as_float(h4.y)),
                                  f2tf(v.z - __uint_as_float(h4.z)),
                                  f2tf(v.w - __uint_as_float(h4.w)));
            *(uint4*)&WsH[r][c4 * 4] = h4;
            *(uint4*)&WsL[r][c4 * 4] = l4;
        }
        __syncthreads();

#pragma unroll
        for (int k8 = 0; k8 < 2; k8++) {
            int ko = k8 * 8;
            unsigned aH[2][4], aL[2][4], bH[4][2], bL[4][2];
#pragma unroll
            for (int mt = 0; mt < 2; mt++) {
                int r = m_base + mt * 16 + grp;
                aH[mt][0] = XsH[r][ko + tig];
                aH[mt][1] = XsH[r + 8][ko + tig];
                aH[mt][2] = XsH[r][ko + tig + 4];
                aH[mt][3] = XsH[r + 8][ko + tig + 4];
                aL[mt][0] = XsL[r][ko + tig];
                aL[mt][1] = XsL[r + 8][ko + tig];
                aL[mt][2] = XsL[r][ko + tig + 4];
                aL[mt][3] = XsL[r + 8][ko + tig + 4];
            }
#pragma unroll
            for (int nt = 0; nt < 4; nt++) {
                int n = n_base + nt * 8 + grp;
                bH[nt][0] = WsH[ko + tig][n];
                bH[nt][1] = WsH[ko + tig + 4][n];
                bL[nt][0] = WsL[ko + tig][n];
                bL[nt][1] = WsL[ko + tig + 4][n];
            }
#define MMA(ci, A, B)                                                          \
    asm volatile(                                                              \
        "mma.sync.aligned.m16n8k8.row.col.f32.tf32.tf32.f32 "                  \
        "{%0,%1,%2,%3}, {%4,%5,%6,%7}, {%8,%9}, {%0,%1,%2,%3};"                \
        : "+f"(ci[0]), "+f"(ci[1]), "+f"(ci[2]), "+f"(ci[3])                   \
        : "r"(A[0]), "r"(A[1]), "r"(A[2]), "r"(A[3]), "r"(B[0]), "r"(B[1]))
#pragma unroll
            for (int mt = 0; mt < 2; mt++)
#pragma unroll
                for (int nt = 0; nt < 4; nt++) {
                    MMA(c[mt][nt], aH[mt], bL[nt]);   // hi*lo
                    MMA(c[mt][nt], aL[mt], bH[nt]);   // lo*hi
                    MMA(c[mt][nt], aH[mt], bH[nt]);   // hi*hi (last: largest term)
                }
#undef MMA
        }
        __syncthreads();
    }

    // ---- epilogue 1: bf16 h ----
#pragma unroll
    for (int mt = 0; mt < 2; mt++) {
        int r_lo = row0 + m_base + mt * 16 + grp;
        int r_hi = r_lo + 8;
#pragma unroll
        for (int nt = 0; nt < 4; nt++) {
            int col = n_base + nt * 8 + 2 * tig;
            if (r_lo < NN)
                *(__nv_bfloat162*)(g_hb + (size_t)r_lo * HIDD + col) =
                    __float22bfloat162_rn(make_float2(c[mt][nt][0], c[mt][nt][1]));
            if (r_hi < NN)
                *(__nv_bfloat162*)(g_hb + (size_t)r_hi * HIDD + col) =
                    __float22bfloat162_rn(make_float2(c[mt][nt][2], c[mt][nt][3]));
        }
    }

    // ---- epilogue 2: fused attention dots (exact fp32) ----
#pragma unroll
    for (int mt = 0; mt < 2; mt++) {
        float sl = 0.f, dl = 0.f, sh = 0.f, dh = 0.f;
#pragma unroll
        for (int nt = 0; nt < 4; nt++) {
            int col = n_base + nt * 8 + 2 * tig;
            float a0 = asrc[col], a1 = asrc[col + 1];
            float d0 = adst[col], d1 = adst[col + 1];
            sl += c[mt][nt][0] * a0 + c[mt][nt][1] * a1;
            dl += c[mt][nt][0] * d0 + c[mt][nt][1] * d1;
            sh += c[mt][nt][2] * a0 + c[mt][nt][3] * a1;
            dh += c[mt][nt][2] * d0 + c[mt][nt][3] * d1;
        }
#pragma unroll
        for (int off = 1; off <= 2; off <<= 1) {     // reduce over tig group
            sl += __shfl_xor_sync(0xffffffffu, sl, off);
            dl += __shfl_xor_sync(0xffffffffu, dl, off);
            sh += __shfl_xor_sync(0xffffffffu, sh, off);
            dh += __shfl_xor_sync(0xffffffffu, dh, off);
        }
        int r_lo = row0 + m_base + mt * 16 + grp;
        if (tig == 0) {
            if (r_lo < NN) {
                g_as[r_lo * NHEAD + head] = sl;
                g_ad[r_lo * NHEAD + head] = dl;
            }
            if (r_lo + 8 < NN) {
                g_as[(r_lo + 8) * NHEAD + head] = sh;
                g_ad[(r_lo + 8) * NHEAD + head] = dh;
            }
        }
    }
}

// ---------------- fused single-pass edge phase (warp per node, 4-way ILP) ---
// out = (sum_e p_e * h[src_e]) / (sum_e p_e); then bias+ReLU+BN.
// pool==1 (last layer): red-add BN output into g_sums instead of writing buf.
__global__ void k_edge(int sel, const float* __restrict__ bias,
                       const float* __restrict__ ga, const float* __restrict__ be,
                       const float* __restrict__ mu, const float* __restrict__ va,
                       int pool) {
    int n = blockIdx.x * 8 + (threadIdx.x >> 5);
    if (n >= NN) return;
    int lane = threadIdx.x & 31;
    int head = lane >> 3;
    int beg = g_ptr[n], end = g_ptr[n + 1];

    float adh = g_ad[n * NHEAD + head];

    float4 a0 = make_float4(0.f, 0.f, 0.f, 0.f);
    float4 a1 = make_float4(0.f, 0.f, 0.f, 0.f);
    float4 a2 = make_float4(0.f, 0.f, 0.f, 0.f);
    float4 a3 = make_float4(0.f, 0.f, 0.f, 0.f);
    float ps0 = 0.f, ps1 = 0.f, ps2 = 0.f, ps3 = 0.f;

    int p = beg;
    // 4-way unrolled main loop: 4 independent load chains -> MLP=4
    for (; p + 4 <= end; p += 4) {
        int s0 = g_csr_src[p];
        int s1 = g_csr_src[p + 1];
        int s2 = g_csr_src[p + 2];
        int s3 = g_csr_src[p + 3];
        float v0 = g_as[s0 * NHEAD + head];
        float v1 = g_as[s1 * NHEAD + head];
        float v2 = g_as[s2 * NHEAD + head];
        float v3 = g_as[s3 * NHEAD + head];
        uint2 u0 = *(const uint2*)(g_hb + (size_t)s0 * HIDD + lane * 4);
        uint2 u1 = *(const uint2*)(g_hb + (size_t)s1 * HIDD + lane * 4);
        uint2 u2 = *(const uint2*)(g_hb + (size_t)s2 * HIDD + lane * 4);
        uint2 u3 = *(const uint2*)(g_hb + (size_t)s3 * HIDD + lane * 4);
        float e0 = __expf(lrelu(v0 + adh));
        float e1 = __expf(lrelu(v1 + adh));
        float e2 = __expf(lrelu(v2 + adh));
        float e3 = __expf(lrelu(v3 + adh));
#define ACC(A, U, E, PS)                                                        \
        {                                                                       \
            float2 f0 = __bfloat1622float2(*reinterpret_cast<__nv_bfloat162*>(&U.x)); \
            float2 f1 = __bfloat1622float2(*reinterpret_cast<__nv_bfloat162*>(&U.y)); \
            A.x += E * f0.x; A.y += E * f0.y;                                   \
            A.z += E * f1.x; A.w += E * f1.y;                                   \
            PS += E;                                                            \
        }
        ACC(a0, u0, e0, ps0)
        ACC(a1, u1, e1, ps1)
        ACC(a2, u2, e2, ps2)
        ACC(a3, u3, e3, ps3)
    }
    for (; p < end; p++) {
        int s0 = g_csr_src[p];
        float v0 = g_as[s0 * NHEAD + head];
        uint2 u0 = *(const uint2*)(g_hb + (size_t)s0 * HIDD + lane * 4);
        float e0 = __expf(lrelu(v0 + adh));
        ACC(a0, u0, e0, ps0)
    }
#undef ACC

    float4 acc = make_float4(a0.x + a1.x + a2.x + a3.x,
                             a0.y + a1.y + a2.y + a3.y,
                             a0.z + a1.z + a2.z + a3.z,
                             a0.w + a1.w + a2.w + a3.w);
    float psum = (ps0 + ps1) + (ps2 + ps3);

    float inv = __fdividef(1.f, psum + 1e-16f);
    float4 b0 = *(const float4*)(bias + lane * 4);
    float4 g4 = *(const float4*)(ga + lane * 4);
    float4 b4 = *(const float4*)(be + lane * 4);
    float4 m4 = *(const float4*)(mu + lane * 4);
    float4 v4 = *(const float4*)(va + lane * 4);
    float4 o;
    o.x = (fmaxf(acc.x * inv + b0.x, 0.f) - m4.x) * (g4.x * rsqrtf(v4.x + BNEPS)) + b4.x;
    o.y = (fmaxf(acc.y * inv + b0.y, 0.f) - m4.y) * (g4.y * rsqrtf(v4.y + BNEPS)) + b4.y;
    o.z = (fmaxf(acc.z * inv + b0.z, 0.f) - m4.z) * (g4.z * rsqrtf(v4.z + BNEPS)) + b4.z;
    o.w = (fmaxf(acc.w * inv + b0.w, 0.f) - m4.w) * (g4.w * rsqrtf(v4.w + BNEPS)) + b4.w;

    if (pool) {
        float* dst = g_sums + (size_t)g_batch[n] * HIDD + lane * 4;
        asm volatile("red.global.add.v4.f32 [%0], {%1,%2,%3,%4};"
                     :: "l"(dst), "f"(o.x), "f"(o.y), "f"(o.z), "f"(o.w)
                     : "memory");
    } else {
        *(float4*)(accbuf(sel) + (size_t)n * HIDD + lane * 4) = o;
    }
}

// ---------------- MLP head ---------------------------------------------------
__global__ void k_head(const float* __restrict__ Wh1, const float* __restrict__ bh1,
                       const float* __restrict__ Wh2, const float* __restrict__ bh2,
                       float* __restrict__ out) {
    __shared__ float pooled[128];
    __shared__ float wsum[2];
    int g = blockIdx.x;
    int t = threadIdx.x;                  // 64 threads
    float inv = 1.0f / fmaxf(g_cnts[g], 1.0f);
    pooled[t]      = g_sums[g * HIDD + t] * inv;
    pooled[t + 64] = g_sums[g * HIDD + 64 + t] * inv;
    __syncthreads();
    float a = 0.f;
#pragma unroll 4
    for (int k = 0; k < 128; k++) a += pooled[k] * Wh1[k * 64 + t];
    a = fmaxf(a + bh1[t], 0.f) * Wh2[t];
#pragma unroll
    for (int off = 16; off >= 1; off >>= 1) a += __shfl_xor_sync(0xffffffffu, a, off);
    if ((t & 31) == 0) wsum[t >> 5] = a;
    __syncthreads();
    if (t == 0) out[g] = wsum[0] + wsum[1] + bh2[0];
}

// ---------------- launcher ---------------------------------------------------
extern "C" void kernel_launch(void* const* d_in, const int* in_sizes, int n_in,
                              void* d_out, int out_size) {
    const float* x     = (const float*)d_in[0];
    const void*  ei    = d_in[1];
    const void*  bt    = d_in[2];
    const float* W     = (const float*)d_in[3];
    const float* asrc  = (const float*)d_in[4];
    const float* adst  = (const float*)d_in[5];
    const float* bias  = (const float*)d_in[6];
    const float* gamma = (const float*)d_in[7];
    const float* beta  = (const float*)d_in[8];
    const float* bnm   = (const float*)d_in[9];
    const float* bnv   = (const float*)d_in[10];
    const float* Wh1   = (const float*)d_in[11];
    const float* bh1   = (const float*)d_in[12];
    const float* Wh2   = (const float*)d_in[13];
    const float* bh2   = (const float*)d_in[14];
    float* out = (float*)d_out;

    const int e_grid    = (ET + 255) / 256;
    const int n_grid    = (NN + 255) / 256;
    const int gemm_grid = (NN + 127) / 128;          // 782
    const int wpn_grid  = (NN + 7) / 8;              // warp-per-node

    // ---- CSR build (once per launch) ----
    k_detect<<<1, 128>>>((const int*)ei);
    k_prep<<<n_grid, 256>>>(bt);
    k_hist<<<e_grid, 256>>>(ei);
    k_scan1<<<NSCAN, SCAN_B>>>();
    k_scan2<<<1, 256>>>();
    k_scan3<<<n_grid, 256>>>();
    k_scatter<<<e_grid, 256>>>(ei);

    // buffer plan: layer0 reads x -> bufA; layer1 bufA -> bufB; layer2 bufB -> pool
    const int accsel[3] = {0, 1, 0};
    const int xsel[3]   = {-1, 0, 1};

    for (int l = 0; l < 3; l++) {
        k_gemm<<<gemm_grid, 512>>>(x, xsel[l], W + (size_t)l * HIDD * HIDD,
                                   asrc + l * NHEAD * HDIM, adst + l * NHEAD * HDIM);
        k_edge<<<wpn_grid, 256>>>(accsel[l], bias + l * HIDD,
                                  gamma + l * HIDD, beta + l * HIDD,
                                  bnm + l * HIDD, bnv + l * HIDD,
                                  l == 2 ? 1 : 0);
    }

    k_head<<<NG, 64>>>(Wh1, bh1, Wh2, bh2, out);
}

// round 16
// speedup vs baseline: 2.5329x; 1.0792x over previous
#include <cuda_runtime.h>
#include <cuda_bf16.h>

#define NN 100000
#define EE 1600000
#define ET (EE + NN)        // 1,700,000 edges incl self loops
#define HIDD 128
#define NHEAD 4
#define HDIM 32
#define NG 128
#define NEG 0.2f
#define BNEPS 1e-5f

#define SCAN_B 512
#define NSCAN ((NN + SCAN_B - 1) / SCAN_B)   // 196

// ---------------- scratch (device globals; no dynamic allocation) ----------
__device__ __nv_bfloat16 g_hb[(size_t)NN * HIDD];  // transformed features (bf16 messages)
__device__ float g_bufA[(size_t)NN * HIDD];  // ping
__device__ float g_bufB[(size_t)NN * HIDD];  // pong
__device__ float g_as[NN * NHEAD];
__device__ float g_ad[NN * NHEAD];
__device__ int   g_csr_src[ET];
__device__ int   g_deg[NN];
__device__ int   g_ptr[NN + 1];
__device__ int   g_wptr[NN];
__device__ int   g_part[256];
__device__ int   g_poff[256];
__device__ int   g_batch[NN];
__device__ float g_sums[NG * HIDD];
__device__ float g_cnts[NG];
__device__ int   g_i64;

// ---------------- helpers ---------------------------------------------------
__device__ __forceinline__ float lrelu(float v) { return v > 0.f ? v : NEG * v; }
__device__ __forceinline__ float* accbuf(int sel) { return sel == 0 ? g_bufA : g_bufB; }

// split-pack two floats into bf16x2 hi word + bf16x2 lo word (v = hi + lo)
__device__ __forceinline__ unsigned packsplit(float x, float y, unsigned& lo) {
    __nv_bfloat162 h = __floats2bfloat162_rn(x, y);
    __nv_bfloat162 l = __floats2bfloat162_rn(x - __bfloat162float(h.x),
                                             y - __bfloat162float(h.y));
    lo = *(unsigned*)&l;
    return *(unsigned*)&h;
}

// ---------------- dtype detection + pool zero --------------------------------
__global__ void k_detect(const int* ei) {
    int t = threadIdx.x;      // 128 threads
    if (t == 0)
        g_i64 = (ei[1] == 0) & (ei[3] == 0) & (ei[5] == 0) & (ei[7] == 0);
    g_cnts[t] = 0.f;
    for (int i = t; i < NG * HIDD; i += 128) g_sums[i] = 0.f;
}

__global__ void k_prep(const void* bt) {
    int i = blockIdx.x * blockDim.x + threadIdx.x;
    if (i >= NN) return;
    g_deg[i] = 0;
    int b = g_i64 ? (int)((const long long*)bt)[i] : ((const int*)bt)[i];
    g_batch[i] = b;
    unsigned m = __match_any_sync(__activemask(), b);
    if (((m >> (threadIdx.x & 31)) & 1) && ((threadIdx.x & 31) == (__ffs(m) - 1)))
        atomicAdd(&g_cnts[b], (float)__popc(m));
}

__device__ __forceinline__ int edge_dst(const void* ei, int e, int f) {
    if (e >= EE) return e - EE;
    return f ? (int)((const long long*)ei)[EE + e] : ((const int*)ei)[EE + e];
}
__device__ __forceinline__ int edge_src(const void* ei, int e, int f) {
    if (e >= EE) return e - EE;
    return f ? (int)((const long long*)ei)[e] : ((const int*)ei)[e];
}

__global__ void k_hist(const void* ei) {
    int e = blockIdx.x * blockDim.x + threadIdx.x;
    if (e >= ET) return;
    atomicAdd(&g_deg[edge_dst(ei, e, g_i64)], 1);
}

__global__ void k_scan1() {
    __shared__ int sm[SCAN_B];
    int i = blockIdx.x * SCAN_B + threadIdx.x;
    int v = (i < NN) ? g_deg[i] : 0;
    sm[threadIdx.x] = v;
    __syncthreads();
    for (int off = 1; off < SCAN_B; off <<= 1) {
        int t = (threadIdx.x >= off) ? sm[threadIdx.x - off] : 0;
        __syncthreads();
        sm[threadIdx.x] += t;
        __syncthreads();
    }
    if (i < NN) g_ptr[i] = sm[threadIdx.x] - v;           // block-local exclusive
    if (threadIdx.x == SCAN_B - 1) g_part[blockIdx.x] = sm[threadIdx.x];
}

__global__ void k_scan2() {   // 1 block, 256 threads, NSCAN<=256
    __shared__ int sm[256];
    int t = threadIdx.x;
    int v = (t < NSCAN) ? g_part[t] : 0;
    sm[t] = v;
    __syncthreads();
    for (int off = 1; off < 256; off <<= 1) {
        int x = (t >= off) ? sm[t - off] : 0;
        __syncthreads();
        sm[t] += x;
        __syncthreads();
    }
    if (t < NSCAN) g_poff[t] = sm[t] - v;                 // exclusive
}

__global__ void k_scan3() {
    int i = blockIdx.x * blockDim.x + threadIdx.x;
    if (i < NN) {
        int v = g_ptr[i] + g_poff[i / SCAN_B];
        g_ptr[i] = v;
        g_wptr[i] = v;
    }
    if (i == 0) g_ptr[NN] = ET;
}

__global__ void k_scatter(const void* ei) {
    int e = blockIdx.x * blockDim.x + threadIdx.x;
    if (e >= ET) return;
    int f = g_i64;
    int d = edge_dst(ei, e, f);
    int s = edge_src(ei, e, f);
    int pos = atomicAdd(&g_wptr[d], 1);
    g_csr_src[pos] = s;
}

// ---------------- split-bf16 3-term tensor GEMM + fused attention epilogue --
// h = X @ W with v = hi + lo (bf16 each); acc += hi*HI + hi*LO + lo*HI.
// mma.m16n8k16.bf16: half the mma + LDS count of the tf32-k8 scheme.
// 512 threads = 16 warps (4x4), block tile 128x128, warp tile 32x32.
__global__ void __launch_bounds__(512, 1) k_gemm(const float* __restrict__ Xext, int xsel,
                                                 const float* __restrict__ W,
                                                 const float* __restrict__ asrc,
                                                 const float* __restrict__ adst) {
    const float* X = (xsel < 0) ? Xext : (xsel == 0 ? g_bufA : g_bufB);
    // X: [row][kpair] packed bf16x2, stride 12 words (conflict-free frag reads)
    __shared__ unsigned XsH[128][12], XsL[128][12];
    // W: [kpair][col] packed bf16x2 (pair = 2 consecutive k rows), stride 136
    __shared__ unsigned WsH[8][136], WsL[8][136];
    int tid = threadIdx.x;
    int lane = tid & 31;
    int wid = tid >> 5;
    int m_base = (wid >> 2) * 32;
    int n_base = (wid & 3) * 32;      // == head * HDIM
    int head = wid & 3;
    int grp = lane >> 2;      // 0..7
    int tig = lane & 3;       // 0..3
    int row0 = blockIdx.x * 128;

    float c[2][4][4];
#pragma unroll
    for (int mt = 0; mt < 2; mt++)
#pragma unroll
        for (int nt = 0; nt < 4; nt++)
#pragma unroll
            for (int i = 0; i < 4; i++) c[mt][nt][i] = 0.f;

    for (int kk = 0; kk < HIDD; kk += 16) {
        // stage X tile [128 x 16]: one float4 per thread -> 2 packed words
        {
            int r = tid >> 2, q = tid & 3;
            int gr = row0 + r;
            float4 v = make_float4(0.f, 0.f, 0.f, 0.f);
            if (gr < NN) v = *(const float4*)(X + (size_t)gr * HIDD + kk + q * 4);
            unsigned l0, l1;
            unsigned h0 = packsplit(v.x, v.y, l0);
            unsigned h1 = packsplit(v.z, v.w, l1);
            *(uint2*)&XsH[r][2 * q] = make_uint2(h0, h1);
            *(uint2*)&XsL[r][2 * q] = make_uint2(l0, l1);
        }
        // stage W tile [16 x 128] as k-pairs: thread -> 2 cols of one k-pair
        {
            int kp = tid >> 6;                 // 0..7
            int c0 = (tid & 63) * 2;           // 0..126
            const float* w0 = W + (size_t)(kk + 2 * kp) * HIDD + c0;
            float2 fa = *(const float2*)w0;            // k even, cols c0,c0+1
            float2 fb = *(const float2*)(w0 + HIDD);   // k odd
            unsigned l0, l1;
            unsigned h0 = packsplit(fa.x, fb.x, l0);   // col c0: (k0,k1)
            unsigned h1 = packsplit(fa.y, fb.y, l1);   // col c0+1
            *(uint2*)&WsH[kp][c0] = make_uint2(h0, h1);
            *(uint2*)&WsL[kp][c0] = make_uint2(l0, l1);
        }
        __syncthreads();

        unsigned aH[2][4], aL[2][4], bH[4][2], bL[4][2];
#pragma unroll
        for (int mt = 0; mt < 2; mt++) {
            int r = m_base + mt * 16 + grp;
            aH[mt][0] = XsH[r][tig];          // rows grp,   k 2tig..+1
            aH[mt][1] = XsH[r + 8][tig];      // rows grp+8
            aH[mt][2] = XsH[r][tig + 4];      // k +8
            aH[mt][3] = XsH[r + 8][tig + 4];
            aL[mt][0] = XsL[r][tig];
            aL[mt][1] = XsL[r + 8][tig];
            aL[mt][2] = XsL[r][tig + 4];
            aL[mt][3] = XsL[r + 8][tig + 4];
        }
#pragma unroll
        for (int nt = 0; nt < 4; nt++) {
            int n = n_base + nt * 8 + grp;
            bH[nt][0] = WsH[tig][n];          // k 2tig..+1
            bH[nt][1] = WsH[tig + 4][n];      // k +8
            bL[nt][0] = WsL[tig][n];
            bL[nt][1] = WsL[tig + 4][n];
        }
#define MMA(ci, A, B)                                                          \
    asm volatile(                                                              \
        "mma.sync.aligned.m16n8k16.row.col.f32.bf16.bf16.f32 "                 \
        "{%0,%1,%2,%3}, {%4,%5,%6,%7}, {%8,%9}, {%0,%1,%2,%3};"                \
        : "+f"(ci[0]), "+f"(ci[1]), "+f"(ci[2]), "+f"(ci[3])                   \
        : "r"(A[0]), "r"(A[1]), "r"(A[2]), "r"(A[3]), "r"(B[0]), "r"(B[1]))
#pragma unroll
        for (int mt = 0; mt < 2; mt++)
#pragma unroll
            for (int nt = 0; nt < 4; nt++) {
                MMA(c[mt][nt], aH[mt], bL[nt]);   // hi*lo
                MMA(c[mt][nt], aL[mt], bH[nt]);   // lo*hi
                MMA(c[mt][nt], aH[mt], bH[nt]);   // hi*hi (last: largest term)
            }
#undef MMA
        __syncthreads();
    }

    // ---- epilogue 1: bf16 h ----
#pragma unroll
    for (int mt = 0; mt < 2; mt++) {
        int r_lo = row0 + m_base + mt * 16 + grp;
        int r_hi = r_lo + 8;
#pragma unroll
        for (int nt = 0; nt < 4; nt++) {
            int col = n_base + nt * 8 + 2 * tig;
            if (r_lo < NN)
                *(__nv_bfloat162*)(g_hb + (size_t)r_lo * HIDD + col) =
                    __float22bfloat162_rn(make_float2(c[mt][nt][0], c[mt][nt][1]));
            if (r_hi < NN)
                *(__nv_bfloat162*)(g_hb + (size_t)r_hi * HIDD + col) =
                    __float22bfloat162_rn(make_float2(c[mt][nt][2], c[mt][nt][3]));
        }
    }

    // ---- epilogue 2: fused attention dots (exact fp32) ----
#pragma unroll
    for (int mt = 0; mt < 2; mt++) {
        float sl = 0.f, dl = 0.f, sh = 0.f, dh = 0.f;
#pragma unroll
        for (int nt = 0; nt < 4; nt++) {
            int col = n_base + nt * 8 + 2 * tig;
            float a0 = asrc[col], a1 = asrc[col + 1];
            float d0 = adst[col], d1 = adst[col + 1];
            sl += c[mt][nt][0] * a0 + c[mt][nt][1] * a1;
            dl += c[mt][nt][0] * d0 + c[mt][nt][1] * d1;
            sh += c[mt][nt][2] * a0 + c[mt][nt][3] * a1;
            dh += c[mt][nt][2] * d0 + c[mt][nt][3] * d1;
        }
#pragma unroll
        for (int off = 1; off <= 2; off <<= 1) {     // reduce over tig group
            sl += __shfl_xor_sync(0xffffffffu, sl, off);
            dl += __shfl_xor_sync(0xffffffffu, dl, off);
            sh += __shfl_xor_sync(0xffffffffu, sh, off);
            dh += __shfl_xor_sync(0xffffffffu, dh, off);
        }
        int r_lo = row0 + m_base + mt * 16 + grp;
        if (tig == 0) {
            if (r_lo < NN) {
                g_as[r_lo * NHEAD + head] = sl;
                g_ad[r_lo * NHEAD + head] = dl;
            }
            if (r_lo + 8 < NN) {
                g_as[(r_lo + 8) * NHEAD + head] = sh;
                g_ad[(r_lo + 8) * NHEAD + head] = dh;
            }
        }
    }
}

// ---------------- fused single-pass edge phase (warp per node, 4-way ILP) ---
__global__ void k_edge(int sel, const float* __restrict__ bias,
                       const float* __restrict__ ga, const float* __restrict__ be,
                       const float* __restrict__ mu, const float* __restrict__ va,
                       int pool) {
    int n = blockIdx.x * 8 + (threadIdx.x >> 5);
    if (n >= NN) return;
    int lane = threadIdx.x & 31;
    int head = lane >> 3;
    int beg = g_ptr[n], end = g_ptr[n + 1];

    float adh = g_ad[n * NHEAD + head];

    float4 a0 = make_float4(0.f, 0.f, 0.f, 0.f);
    float4 a1 = make_float4(0.f, 0.f, 0.f, 0.f);
    float4 a2 = make_float4(0.f, 0.f, 0.f, 0.f);
    float4 a3 = make_float4(0.f, 0.f, 0.f, 0.f);
    float ps0 = 0.f, ps1 = 0.f, ps2 = 0.f, ps3 = 0.f;

    int p = beg;
    for (; p + 4 <= end; p += 4) {
        int s0 = g_csr_src[p];
        int s1 = g_csr_src[p + 1];
        int s2 = g_csr_src[p + 2];
        int s3 = g_csr_src[p + 3];
        float v0 = g_as[s0 * NHEAD + head];
        float v1 = g_as[s1 * NHEAD + head];
        float v2 = g_as[s2 * NHEAD + head];
        float v3 = g_as[s3 * NHEAD + head];
        uint2 u0 = *(const uint2*)(g_hb + (size_t)s0 * HIDD + lane * 4);
        uint2 u1 = *(const uint2*)(g_hb + (size_t)s1 * HIDD + lane * 4);
        uint2 u2 = *(const uint2*)(g_hb + (size_t)s2 * HIDD + lane * 4);
        uint2 u3 = *(const uint2*)(g_hb + (size_t)s3 * HIDD + lane * 4);
        float e0 = __expf(lrelu(v0 + adh));
        float e1 = __expf(lrelu(v1 + adh));
        float e2 = __expf(lrelu(v2 + adh));
        float e3 = __expf(lrelu(v3 + adh));
#define ACC(A, U, E, PS)                                                        \
        {                                                                       \
            float2 f0 = __bfloat1622float2(*reinterpret_cast<__nv_bfloat162*>(&U.x)); \
            float2 f1 = __bfloat1622float2(*reinterpret_cast<__nv_bfloat162*>(&U.y)); \
            A.x += E * f0.x; A.y += E * f0.y;                                   \
            A.z += E * f1.x; A.w += E * f1.y;                                   \
            PS += E;                                                            \
        }
        ACC(a0, u0, e0, ps0)
        ACC(a1, u1, e1, ps1)
        ACC(a2, u2, e2, ps2)
        ACC(a3, u3, e3, ps3)
    }
    for (; p < end; p++) {
        int s0 = g_csr_src[p];
        float v0 = g_as[s0 * NHEAD + head];
        uint2 u0 = *(const uint2*)(g_hb + (size_t)s0 * HIDD + lane * 4);
        float e0 = __expf(lrelu(v0 + adh));
        ACC(a0, u0, e0, ps0)
    }
#undef ACC

    float4 acc = make_float4(a0.x + a1.x + a2.x + a3.x,
                             a0.y + a1.y + a2.y + a3.y,
                             a0.z + a1.z + a2.z + a3.z,
                             a0.w + a1.w + a2.w + a3.w);
    float psum = (ps0 + ps1) + (ps2 + ps3);

    float inv = __fdividef(1.f, psum + 1e-16f);
    float4 b0 = *(const float4*)(bias + lane * 4);
    float4 g4 = *(const float4*)(ga + lane * 4);
    float4 b4 = *(const float4*)(be + lane * 4);
    float4 m4 = *(const float4*)(mu + lane * 4);
    float4 v4 = *(const float4*)(va + lane * 4);
    float4 o;
    o.x = (fmaxf(acc.x * inv + b0.x, 0.f) - m4.x) * (g4.x * rsqrtf(v4.x + BNEPS)) + b4.x;
    o.y = (fmaxf(acc.y * inv + b0.y, 0.f) - m4.y) * (g4.y * rsqrtf(v4.y + BNEPS)) + b4.y;
    o.z = (fmaxf(acc.z * inv + b0.z, 0.f) - m4.z) * (g4.z * rsqrtf(v4.z + BNEPS)) + b4.z;
    o.w = (fmaxf(acc.w * inv + b0.w, 0.f) - m4.w) * (g4.w * rsqrtf(v4.w + BNEPS)) + b4.w;

    if (pool) {
        float* dst = g_sums + (size_t)g_batch[n] * HIDD + lane * 4;
        asm volatile("red.global.add.v4.f32 [%0], {%1,%2,%3,%4};"
                     :: "l"(dst), "f"(o.x), "f"(o.y), "f"(o.z), "f"(o.w)
                     : "memory");
    } else {
        *(float4*)(accbuf(sel) + (size_t)n * HIDD + lane * 4) = o;
    }
}

// ---------------- MLP head ---------------------------------------------------
__global__ void k_head(const float* __restrict__ Wh1, const float* __restrict__ bh1,
                       const float* __restrict__ Wh2, const float* __restrict__ bh2,
                       float* __restrict__ out) {
    __shared__ float pooled[128];
    __shared__ float wsum[2];
    int g = blockIdx.x;
    int t = threadIdx.x;                  // 64 threads
    float inv = 1.0f / fmaxf(g_cnts[g], 1.0f);
    pooled[t]      = g_sums[g * HIDD + t] * inv;
    pooled[t + 64] = g_sums[g * HIDD + 64 + t] * inv;
    __syncthreads();
    float a = 0.f;
#pragma unroll 4
    for (int k = 0; k < 128; k++) a += pooled[k] * Wh1[k * 64 + t];
    a = fmaxf(a + bh1[t], 0.f) * Wh2[t];
#pragma unroll
    for (int off = 16; off >= 1; off >>= 1) a += __shfl_xor_sync(0xffffffffu, a, off);
    if ((t & 31) == 0) wsum[t >> 5] = a;
    __syncthreads();
    if (t == 0) out[g] = wsum[0] + wsum[1] + bh2[0];
}

// ---------------- launcher ---------------------------------------------------
extern "C" void kernel_launch(void* const* d_in, const int* in_sizes, int n_in,
                              void* d_out, int out_size) {
    const float* x     = (const float*)d_in[0];
    const void*  ei    = d_in[1];
    const void*  bt    = d_in[2];
    const float* W     = (const float*)d_in[3];
    const float* asrc  = (const float*)d_in[4];
    const float* adst  = (const float*)d_in[5];
    const float* bias  = (const float*)d_in[6];
    const float* gamma = (const float*)d_in[7];
    const float* beta  = (const float*)d_in[8];
    const float* bnm   = (const float*)d_in[9];
    const float* bnv   = (const float*)d_in[10];
    const float* Wh1   = (const float*)d_in[11];
    const float* bh1   = (const float*)d_in[12];
    const float* Wh2   = (const float*)d_in[13];
    const float* bh2   = (const float*)d_in[14];
    float* out = (float*)d_out;

    const int e_grid    = (ET + 255) / 256;
    const int n_grid    = (NN + 255) / 256;
    const int gemm_grid = (NN + 127) / 128;          // 782
    const int wpn_grid  = (NN + 7) / 8;              // warp-per-node

    // ---- CSR build (once per launch) ----
    k_detect<<<1, 128>>>((const int*)ei);
    k_prep<<<n_grid, 256>>>(bt);
    k_hist<<<e_grid, 256>>>(ei);
    k_scan1<<<NSCAN, SCAN_B>>>();
    k_scan2<<<1, 256>>>();
    k_scan3<<<n_grid, 256>>>();
    k_scatter<<<e_grid, 256>>>(ei);

    // buffer plan: layer0 reads x -> bufA; layer1 bufA -> bufB; layer2 bufB -> pool
    const int accsel[3] = {0, 1, 0};
    const int xsel[3]   = {-1, 0, 1};

    for (int l = 0; l < 3; l++) {
        k_gemm<<<gemm_grid, 512>>>(x, xsel[l], W + (size_t)l * HIDD * HIDD,
                                   asrc + l * NHEAD * HDIM, adst + l * NHEAD * HDIM);
        k_edge<<<wpn_grid, 256>>>(accsel[l], bias + l * HIDD,
                                  gamma + l * HIDD, beta + l * HIDD,
                                  bnm + l * HIDD, bnv + l * HIDD,
                                  l == 2 ? 1 : 0);
    }

    k_head<<<NG, 64>>>(Wh1, bh1, Wh2, bh2, out);
}

// round 17
// speedup vs baseline: 2.5677x; 1.0138x over previous
#include <cuda_runtime.h>
#include <cuda_bf16.h>

#define NN 100000
#define EE 1600000
#define ET (EE + NN)        // 1,700,000 edges incl self loops
#define HIDD 128
#define NHEAD 4
#define HDIM 32
#define NG 128
#define NEG 0.2f
#define BNEPS 1e-5f

#define SCAN_B 512
#define NSCAN ((NN + SCAN_B - 1) / SCAN_B)   // 196

// ---------------- scratch (device globals; no dynamic allocation) ----------
__device__ __nv_bfloat16 g_hb[(size_t)NN * HIDD];  // transformed features (bf16 messages)
__device__ float g_bufA[(size_t)NN * HIDD];  // ping
__device__ float g_bufB[(size_t)NN * HIDD];  // pong
__device__ float g_as[NN * NHEAD];
__device__ float g_ad[NN * NHEAD];
__device__ int   g_csr_src[ET];
__device__ int   g_esrc[ET];
__device__ int   g_edst[ET];
__device__ int   g_deg[NN];
__device__ int   g_ptr[NN + 1];
__device__ int   g_wptr[NN];
__device__ int   g_part[256];
__device__ int   g_poff[256];
__device__ int   g_batch[NN];
__device__ float g_sums[NG * HIDD];
__device__ float g_cnts[NG];

// ---------------- helpers ---------------------------------------------------
__device__ __forceinline__ float lrelu(float v) { return v > 0.f ? v : NEG * v; }
__device__ __forceinline__ float* accbuf(int sel) { return sel == 0 ? g_bufA : g_bufB; }

__device__ __forceinline__ int is_i64(const int* ei) {
    return (ei[1] == 0) & (ei[3] == 0) & (ei[5] == 0) & (ei[7] == 0);
}

// split-pack two floats into bf16x2 hi word + bf16x2 lo word (v = hi + lo)
__device__ __forceinline__ unsigned packsplit(float x, float y, unsigned& lo) {
    __nv_bfloat162 h = __floats2bfloat162_rn(x, y);
    __nv_bfloat162 l = __floats2bfloat162_rn(x - __bfloat162float(h.x),
                                             y - __bfloat162float(h.y));
    lo = *(unsigned*)&l;
    return *(unsigned*)&h;
}

// ---------------- pool-accumulator zero --------------------------------------
__global__ void k_zero() {
    int t = threadIdx.x;      // 128 threads
    g_cnts[t] = 0.f;
    for (int i = t; i < NG * HIDD; i += 128) g_sums[i] = 0.f;
}

__global__ void k_prep(const void* bt, const int* ei) {
    int i = blockIdx.x * blockDim.x + threadIdx.x;
    if (i >= NN) return;
    int f = is_i64(ei);
    g_deg[i] = 0;
    int b = f ? (int)((const long long*)bt)[i] : ((const int*)bt)[i];
    g_batch[i] = b;
    unsigned m = __match_any_sync(__activemask(), b);
    if (((m >> (threadIdx.x & 31)) & 1) && ((threadIdx.x & 31) == (__ffs(m) - 1)))
        atomicAdd(&g_cnts[b], (float)__popc(m));
}

// convert edge list to int32 + degree histogram, one pass
__global__ void k_conv(const void* ei) {
    int e = blockIdx.x * blockDim.x + threadIdx.x;
    if (e >= ET) return;
    int f = is_i64((const int*)ei);
    int s, d;
    if (e < EE) {
        if (f) {
            s = (int)((const long long*)ei)[e];
            d = (int)((const long long*)ei)[EE + e];
        } else {
            s = ((const int*)ei)[e];
            d = ((const int*)ei)[EE + e];
        }
    } else {
        s = d = e - EE;    // self loop
    }
    g_esrc[e] = s;
    g_edst[e] = d;
    atomicAdd(&g_deg[d], 1);
}

__global__ void k_scan1() {
    __shared__ int sm[SCAN_B];
    int i = blockIdx.x * SCAN_B + threadIdx.x;
    int v = (i < NN) ? g_deg[i] : 0;
    sm[threadIdx.x] = v;
    __syncthreads();
    for (int off = 1; off < SCAN_B; off <<= 1) {
        int t = (threadIdx.x >= off) ? sm[threadIdx.x - off] : 0;
        __syncthreads();
        sm[threadIdx.x] += t;
        __syncthreads();
    }
    if (i < NN) g_ptr[i] = sm[threadIdx.x] - v;           // block-local exclusive
    if (threadIdx.x == SCAN_B - 1) g_part[blockIdx.x] = sm[threadIdx.x];
}

__global__ void k_scan2() {   // 1 block, 256 threads, NSCAN<=256
    __shared__ int sm[256];
    int t = threadIdx.x;
    int v = (t < NSCAN) ? g_part[t] : 0;
    sm[t] = v;
    __syncthreads();
    for (int off = 1; off < 256; off <<= 1) {
        int x = (t >= off) ? sm[t - off] : 0;
        __syncthreads();
        sm[t] += x;
        __syncthreads();
    }
    if (t < NSCAN) g_poff[t] = sm[t] - v;                 // exclusive
}

__global__ void k_scan3() {
    int i = blockIdx.x * blockDim.x + threadIdx.x;
    if (i < NN) {
        int v = g_ptr[i] + g_poff[i / SCAN_B];
        g_ptr[i] = v;
        g_wptr[i] = v;
    }
    if (i == 0) g_ptr[NN] = ET;
}

__global__ void k_scatter() {
    int e = blockIdx.x * blockDim.x + threadIdx.x;
    if (e >= ET) return;
    int d = g_edst[e];
    int pos = atomicAdd(&g_wptr[d], 1);
    g_csr_src[pos] = g_esrc[e];
}

// ---------------- split-bf16 3-term tensor GEMM + fused attention epilogue --
__global__ void __launch_bounds__(512, 1) k_gemm(const float* __restrict__ Xext, int xsel,
                                                 const float* __restrict__ W,
                                                 const float* __restrict__ asrc,
                                                 const float* __restrict__ adst) {
    const float* X = (xsel < 0) ? Xext : (xsel == 0 ? g_bufA : g_bufB);
    __shared__ unsigned XsH[128][12], XsL[128][12];
    __shared__ unsigned WsH[8][136], WsL[8][136];
    int tid = threadIdx.x;
    int lane = tid & 31;
    int wid = tid >> 5;
    int m_base = (wid >> 2) * 32;
    int n_base = (wid & 3) * 32;      // == head * HDIM
    int head = wid & 3;
    int grp = lane >> 2;      // 0..7
    int tig = lane & 3;       // 0..3
    int row0 = blockIdx.x * 128;

    float c[2][4][4];
#pragma unroll
    for (int mt = 0; mt < 2; mt++)
#pragma unroll
        for (int nt = 0; nt < 4; nt++)
#pragma unroll
            for (int i = 0; i < 4; i++) c[mt][nt][i] = 0.f;

    for (int kk = 0; kk < HIDD; kk += 16) {
        {
            int r = tid >> 2, q = tid & 3;
            int gr = row0 + r;
            float4 v = make_float4(0.f, 0.f, 0.f, 0.f);
            if (gr < NN) v = *(const float4*)(X + (size_t)gr * HIDD + kk + q * 4);
            unsigned l0, l1;
            unsigned h0 = packsplit(v.x, v.y, l0);
            unsigned h1 = packsplit(v.z, v.w, l1);
            *(uint2*)&XsH[r][2 * q] = make_uint2(h0, h1);
            *(uint2*)&XsL[r][2 * q] = make_uint2(l0, l1);
        }
        {
            int kp = tid >> 6;                 // 0..7
            int c0 = (tid & 63) * 2;           // 0..126
            const float* w0 = W + (size_t)(kk + 2 * kp) * HIDD + c0;
            float2 fa = *(const float2*)w0;            // k even
            float2 fb = *(const float2*)(w0 + HIDD);   // k odd
            unsigned l0, l1;
            unsigned h0 = packsplit(fa.x, fb.x, l0);
            unsigned h1 = packsplit(fa.y, fb.y, l1);
            *(uint2*)&WsH[kp][c0] = make_uint2(h0, h1);
            *(uint2*)&WsL[kp][c0] = make_uint2(l0, l1);
        }
        __syncthreads();

        unsigned aH[2][4], aL[2][4], bH[4][2], bL[4][2];
#pragma unroll
        for (int mt = 0; mt < 2; mt++) {
            int r = m_base + mt * 16 + grp;
            aH[mt][0] = XsH[r][tig];
            aH[mt][1] = XsH[r + 8][tig];
            aH[mt][2] = XsH[r][tig + 4];
            aH[mt][3] = XsH[r + 8][tig + 4];
            aL[mt][0] = XsL[r][tig];
            aL[mt][1] = XsL[r + 8][tig];
            aL[mt][2] = XsL[r][tig + 4];
            aL[mt][3] = XsL[r + 8][tig + 4];
        }
#pragma unroll
        for (int nt = 0; nt < 4; nt++) {
            int n = n_base + nt * 8 + grp;
            bH[nt][0] = WsH[tig][n];
            bH[nt][1] = WsH[tig + 4][n];
            bL[nt][0] = WsL[tig][n];
            bL[nt][1] = WsL[tig + 4][n];
        }
#define MMA(ci, A, B)                                                          \
    asm volatile(                                                              \
        "mma.sync.aligned.m16n8k16.row.col.f32.bf16.bf16.f32 "                 \
        "{%0,%1,%2,%3}, {%4,%5,%6,%7}, {%8,%9}, {%0,%1,%2,%3};"                \
        : "+f"(ci[0]), "+f"(ci[1]), "+f"(ci[2]), "+f"(ci[3])                   \
        : "r"(A[0]), "r"(A[1]), "r"(A[2]), "r"(A[3]), "r"(B[0]), "r"(B[1]))
#pragma unroll
        for (int mt = 0; mt < 2; mt++)
#pragma unroll
            for (int nt = 0; nt < 4; nt++) {
                MMA(c[mt][nt], aH[mt], bL[nt]);   // hi*lo
                MMA(c[mt][nt], aL[mt], bH[nt]);   // lo*hi
                MMA(c[mt][nt], aH[mt], bH[nt]);   // hi*hi (last: largest term)
            }
#undef MMA
        __syncthreads();
    }

    // ---- epilogue 1: bf16 h ----
#pragma unroll
    for (int mt = 0; mt < 2; mt++) {
        int r_lo = row0 + m_base + mt * 16 + grp;
        int r_hi = r_lo + 8;
#pragma unroll
        for (int nt = 0; nt < 4; nt++) {
            int col = n_base + nt * 8 + 2 * tig;
            if (r_lo < NN)
                *(__nv_bfloat162*)(g_hb + (size_t)r_lo * HIDD + col) =
                    __float22bfloat162_rn(make_float2(c[mt][nt][0], c[mt][nt][1]));
            if (r_hi < NN)
                *(__nv_bfloat162*)(g_hb + (size_t)r_hi * HIDD + col) =
                    __float22bfloat162_rn(make_float2(c[mt][nt][2], c[mt][nt][3]));
        }
    }

    // ---- epilogue 2: fused attention dots (exact fp32) ----
#pragma unroll
    for (int mt = 0; mt < 2; mt++) {
        float sl = 0.f, dl = 0.f, sh = 0.f, dh = 0.f;
#pragma unroll
        for (int nt = 0; nt < 4; nt++) {
            int col = n_base + nt * 8 + 2 * tig;
            float a0 = asrc[col], a1 = asrc[col + 1];
            float d0 = adst[col], d1 = adst[col + 1];
            sl += c[mt][nt][0] * a0 + c[mt][nt][1] * a1;
            dl += c[mt][nt][0] * d0 + c[mt][nt][1] * d1;
            sh += c[mt][nt][2] * a0 + c[mt][nt][3] * a1;
            dh += c[mt][nt][2] * d0 + c[mt][nt][3] * d1;
        }
#pragma unroll
        for (int off = 1; off <= 2; off <<= 1) {
            sl += __shfl_xor_sync(0xffffffffu, sl, off);
            dl += __shfl_xor_sync(0xffffffffu, dl, off);
            sh += __shfl_xor_sync(0xffffffffu, sh, off);
            dh += __shfl_xor_sync(0xffffffffu, dh, off);
        }
        int r_lo = row0 + m_base + mt * 16 + grp;
        if (tig == 0) {
            if (r_lo < NN) {
                g_as[r_lo * NHEAD + head] = sl;
                g_ad[r_lo * NHEAD + head] = dl;
            }
            if (r_lo + 8 < NN) {
                g_as[(r_lo + 8) * NHEAD + head] = sh;
                g_ad[(r_lo + 8) * NHEAD + head] = dh;
            }
        }
    }
}

// ---------------- fused single-pass edge phase (warp per node, 4-way ILP) ---
__global__ void k_edge(int sel, const float* __restrict__ bias,
                       const float* __restrict__ ga, const float* __restrict__ be,
                       const float* __restrict__ mu, const float* __restrict__ va,
                       int pool) {
    int n = blockIdx.x * 8 + (threadIdx.x >> 5);
    if (n >= NN) return;
    int lane = threadIdx.x & 31;
    int head = lane >> 3;
    int beg = g_ptr[n], end = g_ptr[n + 1];

    float adh = g_ad[n * NHEAD + head];

    float4 a0 = make_float4(0.f, 0.f, 0.f, 0.f);
    float4 a1 = make_float4(0.f, 0.f, 0.f, 0.f);
    float4 a2 = make_float4(0.f, 0.f, 0.f, 0.f);
    float4 a3 = make_float4(0.f, 0.f, 0.f, 0.f);
    float ps0 = 0.f, ps1 = 0.f, ps2 = 0.f, ps3 = 0.f;

    int p = beg;
    for (; p + 4 <= end; p += 4) {
        int s0 = g_csr_src[p];
        int s1 = g_csr_src[p + 1];
        int s2 = g_csr_src[p + 2];
        int s3 = g_csr_src[p + 3];
        float v0 = g_as[s0 * NHEAD + head];
        float v1 = g_as[s1 * NHEAD + head];
        float v2 = g_as[s2 * NHEAD + head];
        float v3 = g_as[s3 * NHEAD + head];
        uint2 u0 = *(const uint2*)(g_hb + (size_t)s0 * HIDD + lane * 4);
        uint2 u1 = *(const uint2*)(g_hb + (size_t)s1 * HIDD + lane * 4);
        uint2 u2 = *(const uint2*)(g_hb + (size_t)s2 * HIDD + lane * 4);
        uint2 u3 = *(const uint2*)(g_hb + (size_t)s3 * HIDD + lane * 4);
        float e0 = __expf(lrelu(v0 + adh));
        float e1 = __expf(lrelu(v1 + adh));
        float e2 = __expf(lrelu(v2 + adh));
        float e3 = __expf(lrelu(v3 + adh));
#define ACC(A, U, E, PS)                                                        \
        {                                                                       \
            float2 f0 = __bfloat1622float2(*reinterpret_cast<__nv_bfloat162*>(&U.x)); \
            float2 f1 = __bfloat1622float2(*reinterpret_cast<__nv_bfloat162*>(&U.y)); \
            A.x += E * f0.x; A.y += E * f0.y;                                   \
            A.z += E * f1.x; A.w += E * f1.y;                                   \
            PS += E;                                                            \
        }
        ACC(a0, u0, e0, ps0)
        ACC(a1, u1, e1, ps1)
        ACC(a2, u2, e2, ps2)
        ACC(a3, u3, e3, ps3)
    }
    for (; p < end; p++) {
        int s0 = g_csr_src[p];
        float v0 = g_as[s0 * NHEAD + head];
        uint2 u0 = *(const uint2*)(g_hb + (size_t)s0 * HIDD + lane * 4);
        float e0 = __expf(lrelu(v0 + adh));
        ACC(a0, u0, e0, ps0)
    }
#undef ACC

    float4 acc = make_float4(a0.x + a1.x + a2.x + a3.x,
                             a0.y + a1.y + a2.y + a3.y,
                             a0.z + a1.z + a2.z + a3.z,
                             a0.w + a1.w + a2.w + a3.w);
    float psum = (ps0 + ps1) + (ps2 + ps3);

    float inv = __fdividef(1.f, psum + 1e-16f);
    float4 b0 = *(const float4*)(bias + lane * 4);
    float4 g4 = *(const float4*)(ga + lane * 4);
    float4 b4 = *(const float4*)(be + lane * 4);
    float4 m4 = *(const float4*)(mu + lane * 4);
    float4 v4 = *(const float4*)(va + lane * 4);
    float4 o;
    o.x = (fmaxf(acc.x * inv + b0.x, 0.f) - m4.x) * (g4.x * rsqrtf(v4.x + BNEPS)) + b4.x;
    o.y = (fmaxf(acc.y * inv + b0.y, 0.f) - m4.y) * (g4.y * rsqrtf(v4.y + BNEPS)) + b4.y;
    o.z = (fmaxf(acc.z * inv + b0.z, 0.f) - m4.z) * (g4.z * rsqrtf(v4.z + BNEPS)) + b4.z;
    o.w = (fmaxf(acc.w * inv + b0.w, 0.f) - m4.w) * (g4.w * rsqrtf(v4.w + BNEPS)) + b4.w;

    if (pool) {
        float* dst = g_sums + (size_t)g_batch[n] * HIDD + lane * 4;
        asm volatile("red.global.add.v4.f32 [%0], {%1,%2,%3,%4};"
                     :: "l"(dst), "f"(o.x), "f"(o.y), "f"(o.z), "f"(o.w)
                     : "memory");
    } else {
        *(float4*)(accbuf(sel) + (size_t)n * HIDD + lane * 4) = o;
    }
}

// ---------------- MLP head ---------------------------------------------------
__global__ void k_head(const float* __restrict__ Wh1, const float* __restrict__ bh1,
                       const float* __restrict__ Wh2, const float* __restrict__ bh2,
                       float* __restrict__ out) {
    __shared__ float pooled[128];
    __shared__ float wsum[2];
    int g = blockIdx.x;
    int t = threadIdx.x;                  // 64 threads
    float inv = 1.0f / fmaxf(g_cnts[g], 1.0f);
    pooled[t]      = g_sums[g * HIDD + t] * inv;
    pooled[t + 64] = g_sums[g * HIDD + 64 + t] * inv;
    __syncthreads();
    float a = 0.f;
#pragma unroll 4
    for (int k = 0; k < 128; k++) a += pooled[k] * Wh1[k * 64 + t];
    a = fmaxf(a + bh1[t], 0.f) * Wh2[t];
#pragma unroll
    for (int off = 16; off >= 1; off >>= 1) a += __shfl_xor_sync(0xffffffffu, a, off);
    if ((t & 31) == 0) wsum[t >> 5] = a;
    __syncthreads();
    if (t == 0) out[g] = wsum[0] + wsum[1] + bh2[0];
}

// ---------------- launcher ---------------------------------------------------
extern "C" void kernel_launch(void* const* d_in, const int* in_sizes, int n_in,
                              void* d_out, int out_size) {
    const float* x     = (const float*)d_in[0];
    const void*  ei    = d_in[1];
    const void*  bt    = d_in[2];
    const float* W     = (const float*)d_in[3];
    const float* asrc  = (const float*)d_in[4];
    const float* adst  = (const float*)d_in[5];
    const float* bias  = (const float*)d_in[6];
    const float* gamma = (const float*)d_in[7];
    const float* beta  = (const float*)d_in[8];
    const float* bnm   = (const float*)d_in[9];
    const float* bnv   = (const float*)d_in[10];
    const float* Wh1   = (const float*)d_in[11];
    const float* bh1   = (const float*)d_in[12];
    const float* Wh2   = (const float*)d_in[13];
    const float* bh2   = (const float*)d_in[14];
    float* out = (float*)d_out;

    // one-time host-side stream/event setup (no device memory involved)
    static cudaStream_t s2 = nullptr;
    static cudaEvent_t evFork = nullptr, evJoin = nullptr;
    if (s2 == nullptr) {
        cudaStreamCreateWithFlags(&s2, cudaStreamNonBlocking);
        cudaEventCreateWithFlags(&evFork, cudaEventDisableTiming);
        cudaEventCreateWithFlags(&evJoin, cudaEventDisableTiming);
    }

    const int e_grid    = (ET + 255) / 256;
    const int n_grid    = (NN + 255) / 256;
    const int gemm_grid = (NN + 127) / 128;          // 782
    const int wpn_grid  = (NN + 7) / 8;              // warp-per-node

    // ---- fork: layer-0 GEMM (independent of CSR build) on s2 ----
    cudaEventRecord(evFork, 0);
    cudaStreamWaitEvent(s2, evFork, 0);
    k_gemm<<<gemm_grid, 512, 0, s2>>>(x, -1, W, asrc, adst);
    cudaEventRecord(evJoin, s2);

    // ---- CSR build on main stream (concurrent with GEMM0) ----
    k_zero<<<1, 128>>>();
    k_prep<<<n_grid, 256>>>(bt, (const int*)ei);
    k_conv<<<e_grid, 256>>>(ei);
    k_scan1<<<NSCAN, SCAN_B>>>();
    k_scan2<<<1, 256>>>();
    k_scan3<<<n_grid, 256>>>();
    k_scatter<<<e_grid, 256>>>();

    // ---- join before edge layer 0 ----
    cudaStreamWaitEvent(0, evJoin, 0);

    // buffer plan: layer0 x -> bufA; layer1 bufA -> bufB; layer2 bufB -> pool
    const int accsel[3] = {0, 1, 0};
    const int xsel[3]   = {-1, 0, 1};

    for (int l = 0; l < 3; l++) {
        if (l > 0)
            k_gemm<<<gemm_grid, 512>>>(x, xsel[l], W + (size_t)l * HIDD * HIDD,
                                       asrc + l * NHEAD * HDIM, adst + l * NHEAD * HDIM);
        k_edge<<<wpn_grid, 256>>>(accsel[l], bias + l * HIDD,
                                  gamma + l * HIDD, beta + l * HIDD,
                                  bnm + l * HIDD, bnv + l * HIDD,
                                  l == 2 ? 1 : 0);
    }

    k_head<<<NG, 64>>>(Wh1, bh1, Wh2, bh2, out);
}